// round 1
// baseline (speedup 1.0000x reference)
#include <cuda_runtime.h>
#include <cuda_bf16.h>
#include <cstdint>

// Problem constants
#define NTOK 4096      // 2*2048 tokens
#define DHID 2048      // hidden size D
#define IEXP 8192      // expert intermediate I
#define NE   8         // experts
#define G1   64        // gate hidden (E*8)

// ---------------- scratch (device globals; no allocation allowed) ----------------
__device__ float g_T[NTOK * G1];          // tanh(x @ gate_w1)
__device__ float g_coef[NTOK * 4];        // per-token: coef_x, coef_c0, coef_c1, coef_s
__device__ float g_H[(size_t)NTOK * IEXP]; // silu(x@Wg)*(x@Wu)   (134 MB)

// ---------------- helpers ----------------
__device__ __forceinline__ unsigned f2tf32(float x) {
    unsigned y;
    asm("cvt.rna.tf32.f32 %0, %1;" : "=r"(y) : "f"(x));
    return y;
}
__device__ __forceinline__ float siluf(float z) {
    return z * (1.0f / (1.0f + __expf(-z)));
}

#define MMA_TF32(c, a, b)                                                        \
    asm volatile(                                                                \
        "mma.sync.aligned.m16n8k8.row.col.f32.tf32.tf32.f32 "                    \
        "{%0,%1,%2,%3}, {%4,%5,%6,%7}, {%8,%9}, {%0,%1,%2,%3};"                  \
        : "+f"((c)[0]), "+f"((c)[1]), "+f"((c)[2]), "+f"((c)[3])                 \
        : "r"((a)[0]), "r"((a)[1]), "r"((a)[2]), "r"((a)[3]),                    \
          "r"((b)[0]), "r"((b)[1]))

// ======================================================================
// Router stage A: T = tanh(X @ gate_w1)   [4096,2048]@[2048,64] -> [4096,64]
// BM=64 rows per block, full 64 cols, BK=32. 256 threads, 4x4 per thread.
// ======================================================================
__global__ __launch_bounds__(256) void router_gemm_tanh(
    const float* __restrict__ X, const float* __restrict__ W1)
{
    __shared__ float Xs[32][65];   // [k][m], padded
    __shared__ float Ws[32][64];   // [k][n]
    const int tid = threadIdx.x;
    const int tx = tid & 15, ty = tid >> 4;
    const int m0 = blockIdx.x * 64;

    float acc[4][4] = {};
    for (int k0 = 0; k0 < DHID; k0 += 32) {
        __syncthreads();
        // X tile 64x32
        #pragma unroll
        for (int i = 0; i < 8; i++) {
            int e = tid + i * 256;        // 0..2047
            int m = e >> 5, k = e & 31;
            Xs[k][m] = X[(size_t)(m0 + m) * DHID + k0 + k];
        }
        // W1 tile 32x64
        #pragma unroll
        for (int i = 0; i < 8; i++) {
            int e = tid + i * 256;
            int k = e >> 6, n = e & 63;
            Ws[k][n] = W1[(size_t)(k0 + k) * G1 + n];
        }
        __syncthreads();
        #pragma unroll
        for (int k = 0; k < 32; k++) {
            float av[4], bv[4];
            #pragma unroll
            for (int i = 0; i < 4; i++) av[i] = Xs[k][ty * 4 + i];
            #pragma unroll
            for (int j = 0; j < 4; j++) bv[j] = Ws[k][tx * 4 + j];
            #pragma unroll
            for (int i = 0; i < 4; i++)
                #pragma unroll
                for (int j = 0; j < 4; j++)
                    acc[i][j] = fmaf(av[i], bv[j], acc[i][j]);
        }
    }
    #pragma unroll
    for (int i = 0; i < 4; i++)
        #pragma unroll
        for (int j = 0; j < 4; j++)
            g_T[(size_t)(m0 + ty * 4 + i) * G1 + tx * 4 + j] = tanhf(acc[i][j]);
}

// ======================================================================
// Router stage B: per-token logits, softmax, top-2, const-expert gates,
// combine coefficients. One block (128 threads) per token.
// ======================================================================
__global__ __launch_bounds__(128) void router_combine(
    const float* __restrict__ X, const float* __restrict__ W2,
    const float* __restrict__ ceWg, float* __restrict__ logits_out)
{
    const int n = blockIdx.x;
    const int tid = threadIdx.x;
    __shared__ float red[4][128];
    __shared__ float lg[8];

    // const-expert gate dot products: g[e][j] = x . ceWg[e][:, j]
    float pg0 = 0.f, pg1 = 0.f, pg2 = 0.f, pg3 = 0.f;
    for (int k = tid; k < DHID; k += 128) {
        float xv = X[(size_t)n * DHID + k];
        pg0 = fmaf(xv, ceWg[k * 2 + 0], pg0);
        pg1 = fmaf(xv, ceWg[k * 2 + 1], pg1);
        pg2 = fmaf(xv, ceWg[DHID * 2 + k * 2 + 0], pg2);
        pg3 = fmaf(xv, ceWg[DHID * 2 + k * 2 + 1], pg3);
    }
    red[0][tid] = pg0; red[1][tid] = pg1; red[2][tid] = pg2; red[3][tid] = pg3;
    __syncthreads();
    for (int s = 64; s > 0; s >>= 1) {
        if (tid < s) {
            #pragma unroll
            for (int j = 0; j < 4; j++) red[j][tid] += red[j][tid + s];
        }
        __syncthreads();
    }

    // router logits: tanh-layer output (g_T) @ W2
    if (tid < NE) {
        float s = 0.f;
        #pragma unroll 8
        for (int i = 0; i < G1; i++)
            s = fmaf(g_T[(size_t)n * G1 + i], W2[i * NE + tid], s);
        lg[tid] = s;
        logits_out[(size_t)n * NE + tid] = s;
    }
    __syncthreads();

    if (tid == 0) {
        float p[NE];
        float mx = lg[0];
        #pragma unroll
        for (int e = 1; e < NE; e++) mx = fmaxf(mx, lg[e]);
        float sum = 0.f;
        #pragma unroll
        for (int e = 0; e < NE; e++) { p[e] = __expf(lg[e] - mx); sum += p[e]; }
        float inv = 1.f / sum;
        #pragma unroll
        for (int e = 0; e < NE; e++) p[e] *= inv;

        // top-2 (ties: lowest index first, matches jax)
        int i0 = 0;
        #pragma unroll
        for (int e = 1; e < NE; e++) if (p[e] > p[i0]) i0 = e;
        int i1 = (i0 == 0) ? 1 : 0;
        #pragma unroll
        for (int e = 0; e < NE; e++) if (e != i0 && p[e] > p[i1]) i1 = e;

        float w0 = (i0 == NE - 1) ? 0.f : p[i0];
        float w1 = (i1 == NE - 1) ? 0.f : p[i1];
        float wsum = w0 + w1;
        float winv = 1.f / wsum;
        w0 *= winv; w1 *= winv;

        float pe[NE];
        #pragma unroll
        for (int e = 0; e < NE; e++) pe[e] = 0.f;
        pe[i0] += w0; pe[i1] += w1;

        // const-expert 2-way softmaxes
        float cw0x = 1.f / (1.f + __expf(red[1][0] - red[0][0]));
        float cw0c = 1.f - cw0x;
        float cw1x = 1.f / (1.f + __expf(red[3][0] - red[2][0]));
        float cw1c = 1.f - cw1x;

        g_coef[n * 4 + 0] = pe[0] + pe[2] * cw0x + pe[3] * cw1x;  // coef on x
        g_coef[n * 4 + 1] = pe[2] * cw0c;                          // coef on c0
        g_coef[n * 4 + 2] = pe[3] * cw1c;                          // coef on c1
        g_coef[n * 4 + 3] = pe[4] + pe[5] + pe[6] + pe[7];         // coef on swiglu
    }
}

// ======================================================================
// GEMM 1 (fused dual): H = silu(X@Wg) * (X@Wu)
// M=4096, N=8192, K=2048. Tile 128x64x32, 256 threads (8 warps, 4x2).
// TF32 mma.sync m16n8k8, fp32 accumulate. rna conversion at staging.
// ======================================================================
__global__ __launch_bounds__(256) void gemm_gateup(
    const float* __restrict__ A,   // X [4096,2048]
    const float* __restrict__ Bg,  // w_gate [2048,8192]
    const float* __restrict__ Bu)  // w_up   [2048,8192]
{
    __shared__ unsigned Xs[128][36];
    __shared__ unsigned Bs[2][64][36];
    const int tid = threadIdx.x;
    const int lane = tid & 31, wid = tid >> 5;
    const int wm = wid & 3, wn = wid >> 2;     // 4x2 warp grid
    const int g = lane >> 2, tg = lane & 3;
    const int m0 = blockIdx.y * 128, n0 = blockIdx.x * 64;

    float accg[2][4][4] = {};
    float accu[2][4][4] = {};

    for (int k0 = 0; k0 < DHID; k0 += 32) {
        __syncthreads();
        // stage A: 128x32
        #pragma unroll
        for (int i = 0; i < 4; i++) {
            int e = tid + i * 256;             // 0..1023
            int r = e >> 3, kq = e & 7;
            float4 v = *(const float4*)(A + (size_t)(m0 + r) * DHID + k0 + kq * 4);
            Xs[r][kq * 4 + 0] = f2tf32(v.x);
            Xs[r][kq * 4 + 1] = f2tf32(v.y);
            Xs[r][kq * 4 + 2] = f2tf32(v.z);
            Xs[r][kq * 4 + 3] = f2tf32(v.w);
        }
        // stage B tiles: 32x64 each, transposed into [n][k]
        #pragma unroll
        for (int i = 0; i < 2; i++) {
            int e = tid + i * 256;             // 0..511
            int kk = e >> 4, nq = e & 15;
            float4 v = *(const float4*)(Bg + (size_t)(k0 + kk) * IEXP + n0 + nq * 4);
            Bs[0][nq * 4 + 0][kk] = f2tf32(v.x);
            Bs[0][nq * 4 + 1][kk] = f2tf32(v.y);
            Bs[0][nq * 4 + 2][kk] = f2tf32(v.z);
            Bs[0][nq * 4 + 3][kk] = f2tf32(v.w);
            float4 w = *(const float4*)(Bu + (size_t)(k0 + kk) * IEXP + n0 + nq * 4);
            Bs[1][nq * 4 + 0][kk] = f2tf32(w.x);
            Bs[1][nq * 4 + 1][kk] = f2tf32(w.y);
            Bs[1][nq * 4 + 2][kk] = f2tf32(w.z);
            Bs[1][nq * 4 + 3][kk] = f2tf32(w.w);
        }
        __syncthreads();
        #pragma unroll
        for (int ks = 0; ks < 4; ks++) {
            unsigned a[2][4];
            #pragma unroll
            for (int mi = 0; mi < 2; mi++) {
                int r = wm * 32 + mi * 16 + g;
                int c = ks * 8 + tg;
                a[mi][0] = Xs[r][c];     a[mi][1] = Xs[r + 8][c];
                a[mi][2] = Xs[r][c + 4]; a[mi][3] = Xs[r + 8][c + 4];
            }
            unsigned b0[4][2], b1[4][2];
            #pragma unroll
            for (int ni = 0; ni < 4; ni++) {
                int nn = wn * 32 + ni * 8 + g;
                int c = ks * 8 + tg;
                b0[ni][0] = Bs[0][nn][c]; b0[ni][1] = Bs[0][nn][c + 4];
                b1[ni][0] = Bs[1][nn][c]; b1[ni][1] = Bs[1][nn][c + 4];
            }
            #pragma unroll
            for (int mi = 0; mi < 2; mi++)
                #pragma unroll
                for (int ni = 0; ni < 4; ni++) {
                    MMA_TF32(accg[mi][ni], a[mi], b0[ni]);
                    MMA_TF32(accu[mi][ni], a[mi], b1[ni]);
                }
        }
    }

    // epilogue: H = silu(g)*u
    #pragma unroll
    for (int mi = 0; mi < 2; mi++) {
        int mb = m0 + wm * 32 + mi * 16;
        int r1 = mb + g, r2 = mb + g + 8;
        #pragma unroll
        for (int ni = 0; ni < 4; ni++) {
            int nn = n0 + wn * 32 + ni * 8 + 2 * tg;
            float* cg = accg[mi][ni];
            float* cu = accu[mi][ni];
            float2 o1 = make_float2(siluf(cg[0]) * cu[0], siluf(cg[1]) * cu[1]);
            float2 o2 = make_float2(siluf(cg[2]) * cu[2], siluf(cg[3]) * cu[3]);
            *(float2*)(g_H + (size_t)r1 * IEXP + nn) = o1;
            *(float2*)(g_H + (size_t)r2 * IEXP + nn) = o2;
        }
    }
}

// ======================================================================
// GEMM 2: out = coef_s*(H@Wd) + coef_x*x + coef_c0*c0 + coef_c1*c1
// M=4096, N=2048, K=8192. Same tile shape as gemm1, single accumulator.
// ======================================================================
__global__ __launch_bounds__(256) void gemm_down(
    const float* __restrict__ Bd,   // w_down [8192,2048]
    const float* __restrict__ X,    // [4096,2048]
    const float* __restrict__ ceC,  // ce_const [2,2048]
    float* __restrict__ out)
{
    __shared__ unsigned Xs[128][36];
    __shared__ unsigned Bs[64][36];
    const int tid = threadIdx.x;
    const int lane = tid & 31, wid = tid >> 5;
    const int wm = wid & 3, wn = wid >> 2;
    const int g = lane >> 2, tg = lane & 3;
    const int m0 = blockIdx.y * 128, n0 = blockIdx.x * 64;

    float acc[2][4][4] = {};

    for (int k0 = 0; k0 < IEXP; k0 += 32) {
        __syncthreads();
        #pragma unroll
        for (int i = 0; i < 4; i++) {
            int e = tid + i * 256;
            int r = e >> 3, kq = e & 7;
            float4 v = *(const float4*)(g_H + (size_t)(m0 + r) * IEXP + k0 + kq * 4);
            Xs[r][kq * 4 + 0] = f2tf32(v.x);
            Xs[r][kq * 4 + 1] = f2tf32(v.y);
            Xs[r][kq * 4 + 2] = f2tf32(v.z);
            Xs[r][kq * 4 + 3] = f2tf32(v.w);
        }
        #pragma unroll
        for (int i = 0; i < 2; i++) {
            int e = tid + i * 256;
            int kk = e >> 4, nq = e & 15;
            float4 v = *(const float4*)(Bd + (size_t)(k0 + kk) * DHID + n0 + nq * 4);
            Bs[nq * 4 + 0][kk] = f2tf32(v.x);
            Bs[nq * 4 + 1][kk] = f2tf32(v.y);
            Bs[nq * 4 + 2][kk] = f2tf32(v.z);
            Bs[nq * 4 + 3][kk] = f2tf32(v.w);
        }
        __syncthreads();
        #pragma unroll
        for (int ks = 0; ks < 4; ks++) {
            unsigned a[2][4];
            #pragma unroll
            for (int mi = 0; mi < 2; mi++) {
                int r = wm * 32 + mi * 16 + g;
                int c = ks * 8 + tg;
                a[mi][0] = Xs[r][c];     a[mi][1] = Xs[r + 8][c];
                a[mi][2] = Xs[r][c + 4]; a[mi][3] = Xs[r + 8][c + 4];
            }
            unsigned b[4][2];
            #pragma unroll
            for (int ni = 0; ni < 4; ni++) {
                int nn = wn * 32 + ni * 8 + g;
                int c = ks * 8 + tg;
                b[ni][0] = Bs[nn][c]; b[ni][1] = Bs[nn][c + 4];
            }
            #pragma unroll
            for (int mi = 0; mi < 2; mi++)
                #pragma unroll
                for (int ni = 0; ni < 4; ni++)
                    MMA_TF32(acc[mi][ni], a[mi], b[ni]);
        }
    }

    const float* c0 = ceC;
    const float* c1 = ceC + DHID;
    #pragma unroll
    for (int mi = 0; mi < 2; mi++) {
        int mb = m0 + wm * 32 + mi * 16;
        int r1 = mb + g, r2 = mb + g + 8;
        float cx1 = g_coef[r1 * 4 + 0], cc01 = g_coef[r1 * 4 + 1],
              cc11 = g_coef[r1 * 4 + 2], cs1 = g_coef[r1 * 4 + 3];
        float cx2 = g_coef[r2 * 4 + 0], cc02 = g_coef[r2 * 4 + 1],
              cc12 = g_coef[r2 * 4 + 2], cs2 = g_coef[r2 * 4 + 3];
        #pragma unroll
        for (int ni = 0; ni < 4; ni++) {
            int nn = n0 + wn * 32 + ni * 8 + 2 * tg;
            float* c = acc[mi][ni];
            float2 x1 = *(const float2*)(X + (size_t)r1 * DHID + nn);
            float2 x2 = *(const float2*)(X + (size_t)r2 * DHID + nn);
            float2 v0 = *(const float2*)(c0 + nn);
            float2 v1 = *(const float2*)(c1 + nn);
            float2 o1, o2;
            o1.x = cs1 * c[0] + cx1 * x1.x + cc01 * v0.x + cc11 * v1.x;
            o1.y = cs1 * c[1] + cx1 * x1.y + cc01 * v0.y + cc11 * v1.y;
            o2.x = cs2 * c[2] + cx2 * x2.x + cc02 * v0.x + cc12 * v1.x;
            o2.y = cs2 * c[3] + cx2 * x2.y + cc02 * v0.y + cc12 * v1.y;
            *(float2*)(out + (size_t)r1 * DHID + nn) = o1;
            *(float2*)(out + (size_t)r2 * DHID + nn) = o2;
        }
    }
}

// ======================================================================
extern "C" void kernel_launch(void* const* d_in, const int* in_sizes, int n_in,
                              void* d_out, int out_size)
{
    const float* X    = (const float*)d_in[0];  // hidden_states [2,2048,2048]
    const float* W1   = (const float*)d_in[1];  // gate_w1 [2048,64]
    const float* W2   = (const float*)d_in[2];  // gate_w2 [64,8]
    const float* ceWg = (const float*)d_in[3];  // ce_wg [2,2048,2]
    const float* ceC  = (const float*)d_in[4];  // ce_const [2,2048]
    const float* Wg   = (const float*)d_in[5];  // w_gate [2048,8192]
    const float* Wu   = (const float*)d_in[6];  // w_up   [2048,8192]
    const float* Wd   = (const float*)d_in[7];  // w_down [8192,2048]
    float* out = (float*)d_out;
    float* logits = out + (size_t)NTOK * DHID;  // second output, concatenated

    // Router stage A: T = tanh(X @ W1)
    router_gemm_tanh<<<NTOK / 64, 256>>>(X, W1);
    // Router stage B: logits + top-2 + const gates -> coefficients
    router_combine<<<NTOK, 128>>>(X, W2, ceWg,
                                  (out_size > NTOK * DHID) ? logits : nullptr ? logits : logits);
    // GEMM1 fused: H = silu(X@Wg) * (X@Wu)
    gemm_gateup<<<dim3(IEXP / 64, NTOK / 128), 256>>>(X, Wg, Wu);
    // GEMM2 + combine epilogue
    gemm_down<<<dim3(DHID / 64, NTOK / 128), 256>>>(Wd, X, ceC, out);
}

// round 2
// speedup vs baseline: 1.0009x; 1.0009x over previous
#include <cuda_runtime.h>
#include <cuda_bf16.h>
#include <cstdint>

// Problem constants
#define NTOK 4096      // 2*2048 tokens
#define DHID 2048      // hidden size D
#define IEXP 8192      // expert intermediate I
#define NE   8         // experts
#define G1   64        // gate hidden (E*8)

// ---------------- scratch (device globals; no allocation allowed) ----------------
__device__ float g_T[NTOK * G1];          // tanh(x @ gate_w1)
__device__ float g_coef[NTOK * 4];        // per-token: coef_x, coef_c0, coef_c1, coef_s
__device__ float g_H[(size_t)NTOK * IEXP]; // silu(x@Wg)*(x@Wu)   (134 MB)

// ---------------- helpers ----------------
__device__ __forceinline__ unsigned f2tf32(float x) {
    unsigned y;
    asm("cvt.rna.tf32.f32 %0, %1;" : "=r"(y) : "f"(x));
    return y;
}
__device__ __forceinline__ float siluf(float z) {
    return z * (1.0f / (1.0f + __expf(-z)));
}

#define MMA_TF32(c, a, b)                                                        \
    asm volatile(                                                                \
        "mma.sync.aligned.m16n8k8.row.col.f32.tf32.tf32.f32 "                    \
        "{%0,%1,%2,%3}, {%4,%5,%6,%7}, {%8,%9}, {%0,%1,%2,%3};"                  \
        : "+f"((c)[0]), "+f"((c)[1]), "+f"((c)[2]), "+f"((c)[3])                 \
        : "r"((a)[0]), "r"((a)[1]), "r"((a)[2]), "r"((a)[3]),                    \
          "r"((b)[0]), "r"((b)[1]))

// ======================================================================
// Router stage A: T = tanh(X @ gate_w1)   [4096,2048]@[2048,64] -> [4096,64]
// BM=64 rows per block, full 64 cols, BK=32. 256 threads, 4x4 per thread.
// ======================================================================
__global__ __launch_bounds__(256) void router_gemm_tanh(
    const float* __restrict__ X, const float* __restrict__ W1)
{
    __shared__ float Xs[32][65];   // [k][m], padded
    __shared__ float Ws[32][64];   // [k][n]
    const int tid = threadIdx.x;
    const int tx = tid & 15, ty = tid >> 4;
    const int m0 = blockIdx.x * 64;

    float acc[4][4] = {};
    for (int k0 = 0; k0 < DHID; k0 += 32) {
        __syncthreads();
        // X tile 64x32
        #pragma unroll
        for (int i = 0; i < 8; i++) {
            int e = tid + i * 256;        // 0..2047
            int m = e >> 5, k = e & 31;
            Xs[k][m] = X[(size_t)(m0 + m) * DHID + k0 + k];
        }
        // W1 tile 32x64
        #pragma unroll
        for (int i = 0; i < 8; i++) {
            int e = tid + i * 256;
            int k = e >> 6, n = e & 63;
            Ws[k][n] = W1[(size_t)(k0 + k) * G1 + n];
        }
        __syncthreads();
        #pragma unroll
        for (int k = 0; k < 32; k++) {
            float av[4], bv[4];
            #pragma unroll
            for (int i = 0; i < 4; i++) av[i] = Xs[k][ty * 4 + i];
            #pragma unroll
            for (int j = 0; j < 4; j++) bv[j] = Ws[k][tx * 4 + j];
            #pragma unroll
            for (int i = 0; i < 4; i++)
                #pragma unroll
                for (int j = 0; j < 4; j++)
                    acc[i][j] = fmaf(av[i], bv[j], acc[i][j]);
        }
    }
    #pragma unroll
    for (int i = 0; i < 4; i++)
        #pragma unroll
        for (int j = 0; j < 4; j++)
            g_T[(size_t)(m0 + ty * 4 + i) * G1 + tx * 4 + j] = tanhf(acc[i][j]);
}

// ======================================================================
// Router stage B: per-token logits, softmax, top-2, const-expert gates,
// combine coefficients. One block (128 threads) per token.
// ======================================================================
__global__ __launch_bounds__(128) void router_combine(
    const float* __restrict__ X, const float* __restrict__ W2,
    const float* __restrict__ ceWg, float* __restrict__ logits_out)
{
    const int n = blockIdx.x;
    const int tid = threadIdx.x;
    __shared__ float red[4][128];
    __shared__ float lg[8];

    // const-expert gate dot products: g[e][j] = x . ceWg[e][:, j]
    float pg0 = 0.f, pg1 = 0.f, pg2 = 0.f, pg3 = 0.f;
    for (int k = tid; k < DHID; k += 128) {
        float xv = X[(size_t)n * DHID + k];
        pg0 = fmaf(xv, ceWg[k * 2 + 0], pg0);
        pg1 = fmaf(xv, ceWg[k * 2 + 1], pg1);
        pg2 = fmaf(xv, ceWg[DHID * 2 + k * 2 + 0], pg2);
        pg3 = fmaf(xv, ceWg[DHID * 2 + k * 2 + 1], pg3);
    }
    red[0][tid] = pg0; red[1][tid] = pg1; red[2][tid] = pg2; red[3][tid] = pg3;
    __syncthreads();
    for (int s = 64; s > 0; s >>= 1) {
        if (tid < s) {
            #pragma unroll
            for (int j = 0; j < 4; j++) red[j][tid] += red[j][tid + s];
        }
        __syncthreads();
    }

    // router logits: tanh-layer output (g_T) @ W2
    if (tid < NE) {
        float s = 0.f;
        #pragma unroll 8
        for (int i = 0; i < G1; i++)
            s = fmaf(g_T[(size_t)n * G1 + i], W2[i * NE + tid], s);
        lg[tid] = s;
        logits_out[(size_t)n * NE + tid] = s;
    }
    __syncthreads();

    if (tid == 0) {
        float p[NE];
        float mx = lg[0];
        #pragma unroll
        for (int e = 1; e < NE; e++) mx = fmaxf(mx, lg[e]);
        float sum = 0.f;
        #pragma unroll
        for (int e = 0; e < NE; e++) { p[e] = __expf(lg[e] - mx); sum += p[e]; }
        float inv = 1.f / sum;
        #pragma unroll
        for (int e = 0; e < NE; e++) p[e] *= inv;

        // top-2 (ties: lowest index first, matches jax)
        int i0 = 0;
        #pragma unroll
        for (int e = 1; e < NE; e++) if (p[e] > p[i0]) i0 = e;
        int i1 = (i0 == 0) ? 1 : 0;
        #pragma unroll
        for (int e = 0; e < NE; e++) if (e != i0 && p[e] > p[i1]) i1 = e;

        float w0 = (i0 == NE - 1) ? 0.f : p[i0];
        float w1 = (i1 == NE - 1) ? 0.f : p[i1];
        float wsum = w0 + w1;
        float winv = 1.f / wsum;
        w0 *= winv; w1 *= winv;

        float pe[NE];
        #pragma unroll
        for (int e = 0; e < NE; e++) pe[e] = 0.f;
        pe[i0] += w0; pe[i1] += w1;

        // const-expert 2-way softmaxes
        float cw0x = 1.f / (1.f + __expf(red[1][0] - red[0][0]));
        float cw0c = 1.f - cw0x;
        float cw1x = 1.f / (1.f + __expf(red[3][0] - red[2][0]));
        float cw1c = 1.f - cw1x;

        g_coef[n * 4 + 0] = pe[0] + pe[2] * cw0x + pe[3] * cw1x;  // coef on x
        g_coef[n * 4 + 1] = pe[2] * cw0c;                          // coef on c0
        g_coef[n * 4 + 2] = pe[3] * cw1c;                          // coef on c1
        g_coef[n * 4 + 3] = pe[4] + pe[5] + pe[6] + pe[7];         // coef on swiglu
    }
}

// ======================================================================
// GEMM 1 (fused dual): H = silu(X@Wg) * (X@Wu)
// M=4096, N=8192, K=2048. Tile 128x64x32, 256 threads (8 warps, 4x2).
// TF32 mma.sync m16n8k8, fp32 accumulate. rna conversion at staging.
// ======================================================================
__global__ __launch_bounds__(256) void gemm_gateup(
    const float* __restrict__ A,   // X [4096,2048]
    const float* __restrict__ Bg,  // w_gate [2048,8192]
    const float* __restrict__ Bu)  // w_up   [2048,8192]
{
    __shared__ unsigned Xs[128][36];
    __shared__ unsigned Bs[2][64][36];
    const int tid = threadIdx.x;
    const int lane = tid & 31, wid = tid >> 5;
    const int wm = wid & 3, wn = wid >> 2;     // 4x2 warp grid
    const int g = lane >> 2, tg = lane & 3;
    const int m0 = blockIdx.y * 128, n0 = blockIdx.x * 64;

    float accg[2][4][4] = {};
    float accu[2][4][4] = {};

    for (int k0 = 0; k0 < DHID; k0 += 32) {
        __syncthreads();
        // stage A: 128x32
        #pragma unroll
        for (int i = 0; i < 4; i++) {
            int e = tid + i * 256;             // 0..1023
            int r = e >> 3, kq = e & 7;
            float4 v = *(const float4*)(A + (size_t)(m0 + r) * DHID + k0 + kq * 4);
            Xs[r][kq * 4 + 0] = f2tf32(v.x);
            Xs[r][kq * 4 + 1] = f2tf32(v.y);
            Xs[r][kq * 4 + 2] = f2tf32(v.z);
            Xs[r][kq * 4 + 3] = f2tf32(v.w);
        }
        // stage B tiles: 32x64 each, transposed into [n][k]
        #pragma unroll
        for (int i = 0; i < 2; i++) {
            int e = tid + i * 256;             // 0..511
            int kk = e >> 4, nq = e & 15;
            float4 v = *(const float4*)(Bg + (size_t)(k0 + kk) * IEXP + n0 + nq * 4);
            Bs[0][nq * 4 + 0][kk] = f2tf32(v.x);
            Bs[0][nq * 4 + 1][kk] = f2tf32(v.y);
            Bs[0][nq * 4 + 2][kk] = f2tf32(v.z);
            Bs[0][nq * 4 + 3][kk] = f2tf32(v.w);
            float4 w = *(const float4*)(Bu + (size_t)(k0 + kk) * IEXP + n0 + nq * 4);
            Bs[1][nq * 4 + 0][kk] = f2tf32(w.x);
            Bs[1][nq * 4 + 1][kk] = f2tf32(w.y);
            Bs[1][nq * 4 + 2][kk] = f2tf32(w.z);
            Bs[1][nq * 4 + 3][kk] = f2tf32(w.w);
        }
        __syncthreads();
        #pragma unroll
        for (int ks = 0; ks < 4; ks++) {
            unsigned a[2][4];
            #pragma unroll
            for (int mi = 0; mi < 2; mi++) {
                int r = wm * 32 + mi * 16 + g;
                int c = ks * 8 + tg;
                a[mi][0] = Xs[r][c];     a[mi][1] = Xs[r + 8][c];
                a[mi][2] = Xs[r][c + 4]; a[mi][3] = Xs[r + 8][c + 4];
            }
            unsigned b0[4][2], b1[4][2];
            #pragma unroll
            for (int ni = 0; ni < 4; ni++) {
                int nn = wn * 32 + ni * 8 + g;
                int c = ks * 8 + tg;
                b0[ni][0] = Bs[0][nn][c]; b0[ni][1] = Bs[0][nn][c + 4];
                b1[ni][0] = Bs[1][nn][c]; b1[ni][1] = Bs[1][nn][c + 4];
            }
            #pragma unroll
            for (int mi = 0; mi < 2; mi++)
                #pragma unroll
                for (int ni = 0; ni < 4; ni++) {
                    MMA_TF32(accg[mi][ni], a[mi], b0[ni]);
                    MMA_TF32(accu[mi][ni], a[mi], b1[ni]);
                }
        }
    }

    // epilogue: H = silu(g)*u
    #pragma unroll
    for (int mi = 0; mi < 2; mi++) {
        int mb = m0 + wm * 32 + mi * 16;
        int r1 = mb + g, r2 = mb + g + 8;
        #pragma unroll
        for (int ni = 0; ni < 4; ni++) {
            int nn = n0 + wn * 32 + ni * 8 + 2 * tg;
            float* cg = accg[mi][ni];
            float* cu = accu[mi][ni];
            float2 o1 = make_float2(siluf(cg[0]) * cu[0], siluf(cg[1]) * cu[1]);
            float2 o2 = make_float2(siluf(cg[2]) * cu[2], siluf(cg[3]) * cu[3]);
            *(float2*)(g_H + (size_t)r1 * IEXP + nn) = o1;
            *(float2*)(g_H + (size_t)r2 * IEXP + nn) = o2;
        }
    }
}

// ======================================================================
// GEMM 2: out = coef_s*(H@Wd) + coef_x*x + coef_c0*c0 + coef_c1*c1
// M=4096, N=2048, K=8192. Same tile shape as gemm1, single accumulator.
// ======================================================================
__global__ __launch_bounds__(256) void gemm_down(
    const float* __restrict__ Bd,   // w_down [8192,2048]
    const float* __restrict__ X,    // [4096,2048]
    const float* __restrict__ ceC,  // ce_const [2,2048]
    float* __restrict__ out)
{
    __shared__ unsigned Xs[128][36];
    __shared__ unsigned Bs[64][36];
    const int tid = threadIdx.x;
    const int lane = tid & 31, wid = tid >> 5;
    const int wm = wid & 3, wn = wid >> 2;
    const int g = lane >> 2, tg = lane & 3;
    const int m0 = blockIdx.y * 128, n0 = blockIdx.x * 64;

    float acc[2][4][4] = {};

    for (int k0 = 0; k0 < IEXP; k0 += 32) {
        __syncthreads();
        #pragma unroll
        for (int i = 0; i < 4; i++) {
            int e = tid + i * 256;
            int r = e >> 3, kq = e & 7;
            float4 v = *(const float4*)(g_H + (size_t)(m0 + r) * IEXP + k0 + kq * 4);
            Xs[r][kq * 4 + 0] = f2tf32(v.x);
            Xs[r][kq * 4 + 1] = f2tf32(v.y);
            Xs[r][kq * 4 + 2] = f2tf32(v.z);
            Xs[r][kq * 4 + 3] = f2tf32(v.w);
        }
        #pragma unroll
        for (int i = 0; i < 2; i++) {
            int e = tid + i * 256;
            int kk = e >> 4, nq = e & 15;
            float4 v = *(const float4*)(Bd + (size_t)(k0 + kk) * DHID + n0 + nq * 4);
            Bs[nq * 4 + 0][kk] = f2tf32(v.x);
            Bs[nq * 4 + 1][kk] = f2tf32(v.y);
            Bs[nq * 4 + 2][kk] = f2tf32(v.z);
            Bs[nq * 4 + 3][kk] = f2tf32(v.w);
        }
        __syncthreads();
        #pragma unroll
        for (int ks = 0; ks < 4; ks++) {
            unsigned a[2][4];
            #pragma unroll
            for (int mi = 0; mi < 2; mi++) {
                int r = wm * 32 + mi * 16 + g;
                int c = ks * 8 + tg;
                a[mi][0] = Xs[r][c];     a[mi][1] = Xs[r + 8][c];
                a[mi][2] = Xs[r][c + 4]; a[mi][3] = Xs[r + 8][c + 4];
            }
            unsigned b[4][2];
            #pragma unroll
            for (int ni = 0; ni < 4; ni++) {
                int nn = wn * 32 + ni * 8 + g;
                int c = ks * 8 + tg;
                b[ni][0] = Bs[nn][c]; b[ni][1] = Bs[nn][c + 4];
            }
            #pragma unroll
            for (int mi = 0; mi < 2; mi++)
                #pragma unroll
                for (int ni = 0; ni < 4; ni++)
                    MMA_TF32(acc[mi][ni], a[mi], b[ni]);
        }
    }

    const float* c0 = ceC;
    const float* c1 = ceC + DHID;
    #pragma unroll
    for (int mi = 0; mi < 2; mi++) {
        int mb = m0 + wm * 32 + mi * 16;
        int r1 = mb + g, r2 = mb + g + 8;
        float cx1 = g_coef[r1 * 4 + 0], cc01 = g_coef[r1 * 4 + 1],
              cc11 = g_coef[r1 * 4 + 2], cs1 = g_coef[r1 * 4 + 3];
        float cx2 = g_coef[r2 * 4 + 0], cc02 = g_coef[r2 * 4 + 1],
              cc12 = g_coef[r2 * 4 + 2], cs2 = g_coef[r2 * 4 + 3];
        #pragma unroll
        for (int ni = 0; ni < 4; ni++) {
            int nn = n0 + wn * 32 + ni * 8 + 2 * tg;
            float* c = acc[mi][ni];
            float2 x1 = *(const float2*)(X + (size_t)r1 * DHID + nn);
            float2 x2 = *(const float2*)(X + (size_t)r2 * DHID + nn);
            float2 v0 = *(const float2*)(c0 + nn);
            float2 v1 = *(const float2*)(c1 + nn);
            float2 o1, o2;
            o1.x = cs1 * c[0] + cx1 * x1.x + cc01 * v0.x + cc11 * v1.x;
            o1.y = cs1 * c[1] + cx1 * x1.y + cc01 * v0.y + cc11 * v1.y;
            o2.x = cs2 * c[2] + cx2 * x2.x + cc02 * v0.x + cc12 * v1.x;
            o2.y = cs2 * c[3] + cx2 * x2.y + cc02 * v0.y + cc12 * v1.y;
            *(float2*)(out + (size_t)r1 * DHID + nn) = o1;
            *(float2*)(out + (size_t)r2 * DHID + nn) = o2;
        }
    }
}

// ======================================================================
extern "C" void kernel_launch(void* const* d_in, const int* in_sizes, int n_in,
                              void* d_out, int out_size)
{
    const float* X    = (const float*)d_in[0];  // hidden_states [2,2048,2048]
    const float* W1   = (const float*)d_in[1];  // gate_w1 [2048,64]
    const float* W2   = (const float*)d_in[2];  // gate_w2 [64,8]
    const float* ceWg = (const float*)d_in[3];  // ce_wg [2,2048,2]
    const float* ceC  = (const float*)d_in[4];  // ce_const [2,2048]
    const float* Wg   = (const float*)d_in[5];  // w_gate [2048,8192]
    const float* Wu   = (const float*)d_in[6];  // w_up   [2048,8192]
    const float* Wd   = (const float*)d_in[7];  // w_down [8192,2048]
    float* out = (float*)d_out;
    float* logits = out + (size_t)NTOK * DHID;  // second output, concatenated

    // Router stage A: T = tanh(X @ W1)
    router_gemm_tanh<<<NTOK / 64, 256>>>(X, W1);
    // Router stage B: logits + top-2 + const gates -> coefficients
    router_combine<<<NTOK, 128>>>(X, W2, ceWg,
                                  (out_size > NTOK * DHID) ? logits : nullptr ? logits : logits);
    // GEMM1 fused: H = silu(X@Wg) * (X@Wu)
    gemm_gateup<<<dim3(IEXP / 64, NTOK / 128), 256>>>(X, Wg, Wu);
    // GEMM2 + combine epilogue
    gemm_down<<<dim3(DHID / 64, NTOK / 128), 256>>>(Wd, X, ceC, out);
}

// round 4
// speedup vs baseline: 1.2377x; 1.2366x over previous
#include <cuda_runtime.h>
#include <cstdint>

#define NTOK 4096
#define DHID 2048
#define IEXP 8192
#define NE   8
#define G1   64

// ---------------- scratch ----------------
__device__ float g_T[NTOK * G1];
__device__ float g_coef[NTOK * 4];
__device__ float g_H[(size_t)NTOK * IEXP];

// ---------------- helpers ----------------
__device__ __forceinline__ unsigned f2tf32(float x) {
    unsigned y; asm("cvt.rna.tf32.f32 %0, %1;" : "=r"(y) : "f"(x)); return y;
}
__device__ __forceinline__ float siluf(float z) { return z / (1.0f + __expf(-z)); }

#define MMA_TF32(c, a, b)                                                        \
    asm volatile(                                                                \
        "mma.sync.aligned.m16n8k8.row.col.f32.tf32.tf32.f32 "                    \
        "{%0,%1,%2,%3}, {%4,%5,%6,%7}, {%8,%9}, {%0,%1,%2,%3};"                  \
        : "+f"((c)[0]), "+f"((c)[1]), "+f"((c)[2]), "+f"((c)[3])                 \
        : "r"((a)[0]), "r"((a)[1]), "r"((a)[2]), "r"((a)[3]),                    \
          "r"((b)[0]), "r"((b)[1]))

// smem float offsets (per buffer: A 128x36 = 4608, B 32x136 = 4352)
#define OFF_A(b) ((b) * 8960)
#define OFF_B(b) ((b) * 8960 + 4608)
#define SMEM_BYTES 71680   // 2 * 8960 * 4

// ======================================================================
// Router stage A: T = tanh(X @ gate_w1)
// ======================================================================
__global__ __launch_bounds__(256) void router_gemm_tanh(
    const float* __restrict__ X, const float* __restrict__ W1)
{
    __shared__ float Xs[32][65];
    __shared__ float Ws[32][64];
    const int tid = threadIdx.x;
    const int tx = tid & 15, ty = tid >> 4;
    const int m0 = blockIdx.x * 64;

    float acc[4][4] = {};
    for (int k0 = 0; k0 < DHID; k0 += 32) {
        __syncthreads();
        #pragma unroll
        for (int i = 0; i < 8; i++) {
            int e = tid + i * 256;
            Xs[e & 31][e >> 5] = X[(size_t)(m0 + (e >> 5)) * DHID + k0 + (e & 31)];
        }
        #pragma unroll
        for (int i = 0; i < 8; i++) {
            int e = tid + i * 256;
            Ws[e >> 6][e & 63] = W1[(size_t)(k0 + (e >> 6)) * G1 + (e & 63)];
        }
        __syncthreads();
        #pragma unroll
        for (int k = 0; k < 32; k++) {
            float av[4], bv[4];
            #pragma unroll
            for (int i = 0; i < 4; i++) av[i] = Xs[k][ty * 4 + i];
            #pragma unroll
            for (int j = 0; j < 4; j++) bv[j] = Ws[k][tx * 4 + j];
            #pragma unroll
            for (int i = 0; i < 4; i++)
                #pragma unroll
                for (int j = 0; j < 4; j++)
                    acc[i][j] = fmaf(av[i], bv[j], acc[i][j]);
        }
    }
    #pragma unroll
    for (int i = 0; i < 4; i++)
        #pragma unroll
        for (int j = 0; j < 4; j++)
            g_T[(size_t)(m0 + ty * 4 + i) * G1 + tx * 4 + j] = tanhf(acc[i][j]);
}

// ======================================================================
// Router stage B
// ======================================================================
__global__ __launch_bounds__(128) void router_combine(
    const float* __restrict__ X, const float* __restrict__ W2,
    const float* __restrict__ ceWg, float* __restrict__ logits_out)
{
    const int n = blockIdx.x;
    const int tid = threadIdx.x;
    __shared__ float red[4][128];
    __shared__ float lg[8];

    float pg0 = 0.f, pg1 = 0.f, pg2 = 0.f, pg3 = 0.f;
    for (int k = tid; k < DHID; k += 128) {
        float xv = X[(size_t)n * DHID + k];
        pg0 = fmaf(xv, ceWg[k * 2 + 0], pg0);
        pg1 = fmaf(xv, ceWg[k * 2 + 1], pg1);
        pg2 = fmaf(xv, ceWg[DHID * 2 + k * 2 + 0], pg2);
        pg3 = fmaf(xv, ceWg[DHID * 2 + k * 2 + 1], pg3);
    }
    red[0][tid] = pg0; red[1][tid] = pg1; red[2][tid] = pg2; red[3][tid] = pg3;
    __syncthreads();
    for (int s = 64; s > 0; s >>= 1) {
        if (tid < s) {
            #pragma unroll
            for (int j = 0; j < 4; j++) red[j][tid] += red[j][tid + s];
        }
        __syncthreads();
    }
    if (tid < NE) {
        float s = 0.f;
        #pragma unroll 8
        for (int i = 0; i < G1; i++)
            s = fmaf(g_T[(size_t)n * G1 + i], W2[i * NE + tid], s);
        lg[tid] = s;
        logits_out[(size_t)n * NE + tid] = s;
    }
    __syncthreads();
    if (tid == 0) {
        float p[NE];
        float mx = lg[0];
        #pragma unroll
        for (int e = 1; e < NE; e++) mx = fmaxf(mx, lg[e]);
        float sum = 0.f;
        #pragma unroll
        for (int e = 0; e < NE; e++) { p[e] = __expf(lg[e] - mx); sum += p[e]; }
        float inv = 1.f / sum;
        #pragma unroll
        for (int e = 0; e < NE; e++) p[e] *= inv;
        int i0 = 0;
        #pragma unroll
        for (int e = 1; e < NE; e++) if (p[e] > p[i0]) i0 = e;
        int i1 = (i0 == 0) ? 1 : 0;
        #pragma unroll
        for (int e = 0; e < NE; e++) if (e != i0 && p[e] > p[i1]) i1 = e;
        float w0 = (i0 == NE - 1) ? 0.f : p[i0];
        float w1 = (i1 == NE - 1) ? 0.f : p[i1];
        float winv = 1.f / (w0 + w1);
        w0 *= winv; w1 *= winv;
        float pe[NE];
        #pragma unroll
        for (int e = 0; e < NE; e++) pe[e] = 0.f;
        pe[i0] += w0; pe[i1] += w1;
        float cw0x = 1.f / (1.f + __expf(red[1][0] - red[0][0]));
        float cw1x = 1.f / (1.f + __expf(red[3][0] - red[2][0]));
        g_coef[n * 4 + 0] = pe[0] + pe[2] * cw0x + pe[3] * cw1x;
        g_coef[n * 4 + 1] = pe[2] * (1.f - cw0x);
        g_coef[n * 4 + 2] = pe[3] * (1.f - cw1x);
        g_coef[n * 4 + 3] = pe[4] + pe[5] + pe[6] + pe[7];
    }
}

// ======================================================================
// GEMM 1: H = silu(X@Wg) * (X@Wu)
// CTA: M=128 rows x 64 H-cols (mma-N = 128: G[0,64) U[64,128)).
// 8 warps, warp grid 2x4 (m,n), warp tile m64 x n32. K step 32, reg double-buffer.
// ======================================================================
__global__ __launch_bounds__(256, 1) void gemm_gateup(
    const float* __restrict__ X,
    const float* __restrict__ Bg,
    const float* __restrict__ Bu)
{
    extern __shared__ unsigned sm[];
    const int tid = threadIdx.x;
    const int lane = tid & 31, wid = tid >> 5;
    const int wm = wid & 1, wn = wid >> 1;    // 2 x 4
    const int g = lane >> 2, tg = lane & 3;
    const int m0 = blockIdx.x * 128;
    const int n0 = blockIdx.y * 64;
    const int KT = DHID / 32;

    // staging indices
    const int ar = tid >> 3, aq = tid & 7;              // A: row, k-quad
    const int bmat = tid >> 7;                          // 0..1 per 128 threads... (with i offset)
    float acc[4][4][4] = {};

    // preload tile 0 directly
    {
        int k0 = 0;
        #pragma unroll
        for (int i = 0; i < 4; i++) {
            int e = tid + i * 256;
            int r = e >> 3, q = e & 7;
            float4 v = *(const float4*)(X + (size_t)(m0 + r) * DHID + k0 + q * 4);
            uint4 u = make_uint4(f2tf32(v.x), f2tf32(v.y), f2tf32(v.z), f2tf32(v.w));
            *(uint4*)(sm + OFF_A(0) + r * 36 + q * 4) = u;
        }
        #pragma unroll
        for (int i = 0; i < 4; i++) {
            int e = tid + i * 256;
            int mat = e >> 9, rem = e & 511, kk = rem >> 4, nq = rem & 15;
            const float* src = (mat ? Bu : Bg) + (size_t)(k0 + kk) * IEXP + n0 + nq * 4;
            float4 v = *(const float4*)src;
            uint4 u = make_uint4(f2tf32(v.x), f2tf32(v.y), f2tf32(v.z), f2tf32(v.w));
            *(uint4*)(sm + OFF_B(0) + kk * 136 + mat * 64 + nq * 4) = u;
        }
    }
    __syncthreads();

    const int arow = wm * 64;       // warp m base in tile
    const int bcol = wn * 32;       // warp n base in mma space

    for (int kt = 0; kt < KT; kt++) {
        int buf = kt & 1;
        bool more = (kt + 1 < KT);
        float4 pa[4], pb[4];
        if (more) {
            int k0 = (kt + 1) * 32;
            #pragma unroll
            for (int i = 0; i < 4; i++) {
                int e = tid + i * 256;
                int r = e >> 3, q = e & 7;
                pa[i] = *(const float4*)(X + (size_t)(m0 + r) * DHID + k0 + q * 4);
            }
            #pragma unroll
            for (int i = 0; i < 4; i++) {
                int e = tid + i * 256;
                int mat = e >> 9, rem = e & 511, kk = rem >> 4, nq = rem & 15;
                pb[i] = *(const float4*)((mat ? Bu : Bg) + (size_t)(k0 + kk) * IEXP + n0 + nq * 4);
            }
        }
        const unsigned* As = sm + OFF_A(buf);
        const unsigned* Bs = sm + OFF_B(buf);
        #pragma unroll
        for (int ks = 0; ks < 4; ks++) {
            int c = ks * 8 + tg;
            unsigned a[4][4];
            #pragma unroll
            for (int mi = 0; mi < 4; mi++) {
                int r = arow + mi * 16 + g;
                a[mi][0] = As[r * 36 + c];
                a[mi][1] = As[(r + 8) * 36 + c];
                a[mi][2] = As[r * 36 + c + 4];
                a[mi][3] = As[(r + 8) * 36 + c + 4];
            }
            unsigned b[4][2];
            #pragma unroll
            for (int ni = 0; ni < 4; ni++) {
                int nn = bcol + ni * 8 + g;
                b[ni][0] = Bs[c * 136 + nn];
                b[ni][1] = Bs[(c + 4) * 136 + nn];
            }
            #pragma unroll
            for (int mi = 0; mi < 4; mi++)
                #pragma unroll
                for (int ni = 0; ni < 4; ni++)
                    MMA_TF32(acc[mi][ni], a[mi], b[ni]);
        }
        __syncthreads();
        if (more) {
            int nb = buf ^ 1;
            #pragma unroll
            for (int i = 0; i < 4; i++) {
                int e = tid + i * 256;
                int r = e >> 3, q = e & 7;
                uint4 u = make_uint4(f2tf32(pa[i].x), f2tf32(pa[i].y), f2tf32(pa[i].z), f2tf32(pa[i].w));
                *(uint4*)(sm + OFF_A(nb) + r * 36 + q * 4) = u;
            }
            #pragma unroll
            for (int i = 0; i < 4; i++) {
                int e = tid + i * 256;
                int mat = e >> 9, rem = e & 511, kk = rem >> 4, nq = rem & 15;
                uint4 u = make_uint4(f2tf32(pb[i].x), f2tf32(pb[i].y), f2tf32(pb[i].z), f2tf32(pb[i].w));
                *(uint4*)(sm + OFF_B(nb) + kk * 136 + mat * 64 + nq * 4) = u;
            }
            __syncthreads();
        }
    }

    // epilogue: acc -> smem [128][132], pair G/U, write g_H
    __syncthreads();
    float* Hs = (float*)sm;
    #pragma unroll
    for (int mi = 0; mi < 4; mi++) {
        int r1 = arow + mi * 16 + g, r2 = r1 + 8;
        #pragma unroll
        for (int ni = 0; ni < 4; ni++) {
            int cc = bcol + ni * 8 + 2 * tg;
            float* c = acc[mi][ni];
            *(float2*)(Hs + r1 * 132 + cc) = make_float2(c[0], c[1]);
            *(float2*)(Hs + r2 * 132 + cc) = make_float2(c[2], c[3]);
        }
    }
    __syncthreads();
    #pragma unroll
    for (int i = 0; i < 32; i++) {
        int e = tid + i * 256;
        int r = e >> 6, cc = e & 63;
        float gv = Hs[r * 132 + cc];
        float uv = Hs[r * 132 + 64 + cc];
        g_H[(size_t)(m0 + r) * IEXP + n0 + cc] = siluf(gv) * uv;
    }
}

// ======================================================================
// GEMM 2: out = cs*(H@Wd) + cx*x + cc0*c0 + cc1*c1
// CTA: M=128 x N=128, warp tile m64 x n32. K=8192, step 32.
// ======================================================================
__global__ __launch_bounds__(256, 1) void gemm_down(
    const float* __restrict__ Bd,
    const float* __restrict__ X,
    const float* __restrict__ ceC,
    float* __restrict__ out)
{
    extern __shared__ unsigned sm[];
    const int tid = threadIdx.x;
    const int lane = tid & 31, wid = tid >> 5;
    const int wm = wid & 1, wn = wid >> 1;
    const int g = lane >> 2, tg = lane & 3;
    const int m0 = blockIdx.x * 128;
    const int n0 = blockIdx.y * 128;
    const int KT = IEXP / 32;

    float acc[4][4][4] = {};

    {
        int k0 = 0;
        #pragma unroll
        for (int i = 0; i < 4; i++) {
            int e = tid + i * 256;
            int r = e >> 3, q = e & 7;
            float4 v = *(const float4*)(g_H + (size_t)(m0 + r) * IEXP + k0 + q * 4);
            uint4 u = make_uint4(f2tf32(v.x), f2tf32(v.y), f2tf32(v.z), f2tf32(v.w));
            *(uint4*)(sm + OFF_A(0) + r * 36 + q * 4) = u;
        }
        #pragma unroll
        for (int i = 0; i < 4; i++) {
            int e = tid + i * 256;
            int kk = e >> 5, nq = e & 31;
            float4 v = *(const float4*)(Bd + (size_t)(k0 + kk) * DHID + n0 + nq * 4);
            uint4 u = make_uint4(f2tf32(v.x), f2tf32(v.y), f2tf32(v.z), f2tf32(v.w));
            *(uint4*)(sm + OFF_B(0) + kk * 136 + nq * 4) = u;
        }
    }
    __syncthreads();

    const int arow = wm * 64;
    const int bcol = wn * 32;

    for (int kt = 0; kt < KT; kt++) {
        int buf = kt & 1;
        bool more = (kt + 1 < KT);
        float4 pa[4], pb[4];
        if (more) {
            int k0 = (kt + 1) * 32;
            #pragma unroll
            for (int i = 0; i < 4; i++) {
                int e = tid + i * 256;
                int r = e >> 3, q = e & 7;
                pa[i] = *(const float4*)(g_H + (size_t)(m0 + r) * IEXP + k0 + q * 4);
            }
            #pragma unroll
            for (int i = 0; i < 4; i++) {
                int e = tid + i * 256;
                int kk = e >> 5, nq = e & 31;
                pb[i] = *(const float4*)(Bd + (size_t)(k0 + kk) * DHID + n0 + nq * 4);
            }
        }
        const unsigned* As = sm + OFF_A(buf);
        const unsigned* Bs = sm + OFF_B(buf);
        #pragma unroll
        for (int ks = 0; ks < 4; ks++) {
            int c = ks * 8 + tg;
            unsigned a[4][4];
            #pragma unroll
            for (int mi = 0; mi < 4; mi++) {
                int r = arow + mi * 16 + g;
                a[mi][0] = As[r * 36 + c];
                a[mi][1] = As[(r + 8) * 36 + c];
                a[mi][2] = As[r * 36 + c + 4];
                a[mi][3] = As[(r + 8) * 36 + c + 4];
            }
            unsigned b[4][2];
            #pragma unroll
            for (int ni = 0; ni < 4; ni++) {
                int nn = bcol + ni * 8 + g;
                b[ni][0] = Bs[c * 136 + nn];
                b[ni][1] = Bs[(c + 4) * 136 + nn];
            }
            #pragma unroll
            for (int mi = 0; mi < 4; mi++)
                #pragma unroll
                for (int ni = 0; ni < 4; ni++)
                    MMA_TF32(acc[mi][ni], a[mi], b[ni]);
        }
        __syncthreads();
        if (more) {
            int nb = buf ^ 1;
            #pragma unroll
            for (int i = 0; i < 4; i++) {
                int e = tid + i * 256;
                int r = e >> 3, q = e & 7;
                uint4 u = make_uint4(f2tf32(pa[i].x), f2tf32(pa[i].y), f2tf32(pa[i].z), f2tf32(pa[i].w));
                *(uint4*)(sm + OFF_A(nb) + r * 36 + q * 4) = u;
            }
            #pragma unroll
            for (int i = 0; i < 4; i++) {
                int e = tid + i * 256;
                int kk = e >> 5, nq = e & 31;
                uint4 u = make_uint4(f2tf32(pb[i].x), f2tf32(pb[i].y), f2tf32(pb[i].z), f2tf32(pb[i].w));
                *(uint4*)(sm + OFF_B(nb) + kk * 136 + nq * 4) = u;
            }
            __syncthreads();
        }
    }

    // epilogue: fold routing coefficients, direct from regs
    const float* c0 = ceC;
    const float* c1 = ceC + DHID;
    #pragma unroll
    for (int mi = 0; mi < 4; mi++) {
        int r1 = m0 + arow + mi * 16 + g;
        int r2 = r1 + 8;
        float cx1 = g_coef[r1 * 4 + 0], cc01 = g_coef[r1 * 4 + 1],
              cc11 = g_coef[r1 * 4 + 2], cs1 = g_coef[r1 * 4 + 3];
        float cx2 = g_coef[r2 * 4 + 0], cc02 = g_coef[r2 * 4 + 1],
              cc12 = g_coef[r2 * 4 + 2], cs2 = g_coef[r2 * 4 + 3];
        #pragma unroll
        for (int ni = 0; ni < 4; ni++) {
            int nn = n0 + bcol + ni * 8 + 2 * tg;
            float* c = acc[mi][ni];
            float2 x1 = *(const float2*)(X + (size_t)r1 * DHID + nn);
            float2 x2 = *(const float2*)(X + (size_t)r2 * DHID + nn);
            float2 v0 = *(const float2*)(c0 + nn);
            float2 v1 = *(const float2*)(c1 + nn);
            float2 o1, o2;
            o1.x = cs1 * c[0] + cx1 * x1.x + cc01 * v0.x + cc11 * v1.x;
            o1.y = cs1 * c[1] + cx1 * x1.y + cc01 * v0.y + cc11 * v1.y;
            o2.x = cs2 * c[2] + cx2 * x2.x + cc02 * v0.x + cc12 * v1.x;
            o2.y = cs2 * c[3] + cx2 * x2.y + cc02 * v0.y + cc12 * v1.y;
            *(float2*)(out + (size_t)r1 * DHID + nn) = o1;
            *(float2*)(out + (size_t)r2 * DHID + nn) = o2;
        }
    }
}

// ======================================================================
extern "C" void kernel_launch(void* const* d_in, const int* in_sizes, int n_in,
                              void* d_out, int out_size)
{
    const float* X    = (const float*)d_in[0];
    const float* W1   = (const float*)d_in[1];
    const float* W2   = (const float*)d_in[2];
    const float* ceWg = (const float*)d_in[3];
    const float* ceC  = (const float*)d_in[4];
    const float* Wg   = (const float*)d_in[5];
    const float* Wu   = (const float*)d_in[6];
    const float* Wd   = (const float*)d_in[7];
    float* out = (float*)d_out;
    float* logits = out + (size_t)NTOK * DHID;

    cudaFuncSetAttribute(gemm_gateup, cudaFuncAttributeMaxDynamicSharedMemorySize, SMEM_BYTES);
    cudaFuncSetAttribute(gemm_down, cudaFuncAttributeMaxDynamicSharedMemorySize, SMEM_BYTES);

    router_gemm_tanh<<<NTOK / 64, 256>>>(X, W1);
    router_combine<<<NTOK, 128>>>(X, W2, ceWg, logits);

    gemm_gateup<<<dim3(NTOK / 128, IEXP / 64), 256, SMEM_BYTES>>>(X, Wg, Wu);
    gemm_down<<<dim3(NTOK / 128, DHID / 128), 256, SMEM_BYTES>>>(Wd, X, ceC, out);
}

// round 5
// speedup vs baseline: 1.5979x; 1.2910x over previous
#include <cuda_runtime.h>
#include <cstdint>

#define NTOK 4096
#define DHID 2048
#define IEXP 8192
#define NE   8
#define G1   64

// ---------------- scratch ----------------
__device__ float g_T[NTOK * G1];
__device__ float g_coef[NTOK * 4];
__device__ float g_X32[(size_t)NTOK * DHID];
__device__ float g_Wg32[(size_t)DHID * IEXP];
__device__ float g_Wu32[(size_t)DHID * IEXP];
__device__ float g_Wd32[(size_t)IEXP * DHID];
__device__ float g_H[(size_t)NTOK * IEXP];

// ---------------- helpers ----------------
__device__ __forceinline__ unsigned f2tf32(float x) {
    unsigned y; asm("cvt.rna.tf32.f32 %0, %1;" : "=r"(y) : "f"(x)); return y;
}
__device__ __forceinline__ float siluf(float z) { return z / (1.0f + __expf(-z)); }
__device__ __forceinline__ uint32_t smem_u32(const void* p) {
    uint32_t a;
    asm("{ .reg .u64 t; cvta.to.shared.u64 t, %1; cvt.u32.u64 %0, t; }" : "=r"(a) : "l"(p));
    return a;
}
__device__ __forceinline__ void cpa16(uint32_t d, const float* s) {
    asm volatile("cp.async.cg.shared.global [%0], [%1], 16;" :: "r"(d), "l"(s));
}
#define CPA_COMMIT() asm volatile("cp.async.commit_group;" ::: "memory")
#define CPA_WAIT(n)  asm volatile("cp.async.wait_group %0;" :: "n"(n) : "memory")

#define MMA_TF32(c, a, b)                                                        \
    asm volatile(                                                                \
        "mma.sync.aligned.m16n8k8.row.col.f32.tf32.tf32.f32 "                    \
        "{%0,%1,%2,%3}, {%4,%5,%6,%7}, {%8,%9}, {%0,%1,%2,%3};"                  \
        : "+f"((c)[0]), "+f"((c)[1]), "+f"((c)[2]), "+f"((c)[3])                 \
        : "r"((a)[0]), "r"((a)[1]), "r"((a)[2]), "r"((a)[3]),                    \
          "r"((b)[0]), "r"((b)[1]))

// per stage (floats): A 128x36 = 4608, B 32x136 = 4352 -> 8960
#define OFF_A(s) ((s) * 8960)
#define OFF_B(s) ((s) * 8960 + 4608)
#define SMEM_BYTES (3 * 8960 * 4)   // 107520

// ======================================================================
// Prep: elementwise tf32 rounding
// ======================================================================
__global__ __launch_bounds__(256) void round_tf32_k(
    const float* __restrict__ src, float* __restrict__ dst, int n4)
{
    int i = blockIdx.x * blockDim.x + threadIdx.x;
    int stride = gridDim.x * blockDim.x;
    for (; i < n4; i += stride) {
        float4 v = ((const float4*)src)[i];
        v.x = __uint_as_float(f2tf32(v.x)); v.y = __uint_as_float(f2tf32(v.y));
        v.z = __uint_as_float(f2tf32(v.z)); v.w = __uint_as_float(f2tf32(v.w));
        ((float4*)dst)[i] = v;
    }
}

// ======================================================================
// Router stage A: T = tanh(X @ gate_w1)
// ======================================================================
__global__ __launch_bounds__(256) void router_gemm_tanh(
    const float* __restrict__ X, const float* __restrict__ W1)
{
    __shared__ float Xs[32][65];
    __shared__ float Ws[32][64];
    const int tid = threadIdx.x;
    const int tx = tid & 15, ty = tid >> 4;
    const int m0 = blockIdx.x * 64;

    float acc[4][4] = {};
    for (int k0 = 0; k0 < DHID; k0 += 32) {
        __syncthreads();
        #pragma unroll
        for (int i = 0; i < 8; i++) {
            int e = tid + i * 256;
            Xs[e & 31][e >> 5] = X[(size_t)(m0 + (e >> 5)) * DHID + k0 + (e & 31)];
        }
        #pragma unroll
        for (int i = 0; i < 8; i++) {
            int e = tid + i * 256;
            Ws[e >> 6][e & 63] = W1[(size_t)(k0 + (e >> 6)) * G1 + (e & 63)];
        }
        __syncthreads();
        #pragma unroll
        for (int k = 0; k < 32; k++) {
            float av[4], bv[4];
            #pragma unroll
            for (int i = 0; i < 4; i++) av[i] = Xs[k][ty * 4 + i];
            #pragma unroll
            for (int j = 0; j < 4; j++) bv[j] = Ws[k][tx * 4 + j];
            #pragma unroll
            for (int i = 0; i < 4; i++)
                #pragma unroll
                for (int j = 0; j < 4; j++)
                    acc[i][j] = fmaf(av[i], bv[j], acc[i][j]);
        }
    }
    #pragma unroll
    for (int i = 0; i < 4; i++)
        #pragma unroll
        for (int j = 0; j < 4; j++)
            g_T[(size_t)(m0 + ty * 4 + i) * G1 + tx * 4 + j] = tanhf(acc[i][j]);
}

// ======================================================================
// Router stage B
// ======================================================================
__global__ __launch_bounds__(128) void router_combine(
    const float* __restrict__ X, const float* __restrict__ W2,
    const float* __restrict__ ceWg, float* __restrict__ logits_out)
{
    const int n = blockIdx.x;
    const int tid = threadIdx.x;
    __shared__ float red[4][128];
    __shared__ float lg[8];

    float pg0 = 0.f, pg1 = 0.f, pg2 = 0.f, pg3 = 0.f;
    for (int k = tid; k < DHID; k += 128) {
        float xv = X[(size_t)n * DHID + k];
        pg0 = fmaf(xv, ceWg[k * 2 + 0], pg0);
        pg1 = fmaf(xv, ceWg[k * 2 + 1], pg1);
        pg2 = fmaf(xv, ceWg[DHID * 2 + k * 2 + 0], pg2);
        pg3 = fmaf(xv, ceWg[DHID * 2 + k * 2 + 1], pg3);
    }
    red[0][tid] = pg0; red[1][tid] = pg1; red[2][tid] = pg2; red[3][tid] = pg3;
    __syncthreads();
    for (int s = 64; s > 0; s >>= 1) {
        if (tid < s) {
            #pragma unroll
            for (int j = 0; j < 4; j++) red[j][tid] += red[j][tid + s];
        }
        __syncthreads();
    }
    if (tid < NE) {
        float s = 0.f;
        #pragma unroll 8
        for (int i = 0; i < G1; i++)
            s = fmaf(g_T[(size_t)n * G1 + i], W2[i * NE + tid], s);
        lg[tid] = s;
        logits_out[(size_t)n * NE + tid] = s;
    }
    __syncthreads();
    if (tid == 0) {
        float p[NE];
        float mx = lg[0];
        #pragma unroll
        for (int e = 1; e < NE; e++) mx = fmaxf(mx, lg[e]);
        float sum = 0.f;
        #pragma unroll
        for (int e = 0; e < NE; e++) { p[e] = __expf(lg[e] - mx); sum += p[e]; }
        float inv = 1.f / sum;
        #pragma unroll
        for (int e = 0; e < NE; e++) p[e] *= inv;
        int i0 = 0;
        #pragma unroll
        for (int e = 1; e < NE; e++) if (p[e] > p[i0]) i0 = e;
        int i1 = (i0 == 0) ? 1 : 0;
        #pragma unroll
        for (int e = 0; e < NE; e++) if (e != i0 && p[e] > p[i1]) i1 = e;
        float w0 = (i0 == NE - 1) ? 0.f : p[i0];
        float w1 = (i1 == NE - 1) ? 0.f : p[i1];
        float winv = 1.f / (w0 + w1);
        w0 *= winv; w1 *= winv;
        float pe[NE];
        #pragma unroll
        for (int e = 0; e < NE; e++) pe[e] = 0.f;
        pe[i0] += w0; pe[i1] += w1;
        float cw0x = 1.f / (1.f + __expf(red[1][0] - red[0][0]));
        float cw1x = 1.f / (1.f + __expf(red[3][0] - red[2][0]));
        g_coef[n * 4 + 0] = pe[0] + pe[2] * cw0x + pe[3] * cw1x;
        g_coef[n * 4 + 1] = pe[2] * (1.f - cw0x);
        g_coef[n * 4 + 2] = pe[3] * (1.f - cw1x);
        g_coef[n * 4 + 3] = pe[4] + pe[5] + pe[6] + pe[7];
    }
}

// ======================================================================
// GEMM 1: H = silu(X@Wg) * (X@Wu)
// CTA M=128 x 64 H-cols (mma N=128: G[0,64)|U[64,128)). 8 warps 2x4,
// warp tile m64xn32. cp.async 3-stage pipeline, K step 32.
// ======================================================================
__global__ __launch_bounds__(256, 2) void gemm_gateup()
{
    extern __shared__ unsigned sm[];
    const uint32_t sa = smem_u32(sm);
    const int tid = threadIdx.x;
    const int lane = tid & 31, wid = tid >> 5;
    const int wm = wid & 1, wn = wid >> 1;
    const int g = lane >> 2, tg = lane & 3;
    const int m0 = blockIdx.x * 128;
    const int n0 = blockIdx.y * 64;
    const int KT = DHID / 32;

    float acc[4][4][4] = {};

    auto issue = [&](int kt) {
        int s = kt % 3, k0 = kt * 32;
        #pragma unroll
        for (int i = 0; i < 4; i++) {
            int e = tid + i * 256;
            int r = e >> 3, q = e & 7;
            cpa16(sa + (OFF_A(s) + r * 36 + q * 4) * 4,
                  g_X32 + (size_t)(m0 + r) * DHID + k0 + q * 4);
        }
        #pragma unroll
        for (int i = 0; i < 4; i++) {
            int e = tid + i * 256;
            int kk = e >> 5, c8 = e & 31;
            const float* src = (c8 < 16)
                ? g_Wg32 + (size_t)(k0 + kk) * IEXP + n0 + c8 * 4
                : g_Wu32 + (size_t)(k0 + kk) * IEXP + n0 + (c8 - 16) * 4;
            cpa16(sa + (OFF_B(s) + kk * 136 + c8 * 4) * 4, src);
        }
        CPA_COMMIT();
    };

    issue(0); issue(1);
    const int arow = wm * 64;
    const int bcol = wn * 32;

    for (int kt = 0; kt < KT; kt++) {
        if (kt < KT - 1) CPA_WAIT(1); else CPA_WAIT(0);
        __syncthreads();
        if (kt + 2 < KT) issue(kt + 2);
        const unsigned* As = sm + OFF_A(kt % 3);
        const unsigned* Bs = sm + OFF_B(kt % 3);
        #pragma unroll
        for (int ks = 0; ks < 4; ks++) {
            int c = ks * 8 + tg;
            unsigned a[4][4];
            #pragma unroll
            for (int mi = 0; mi < 4; mi++) {
                int r = arow + mi * 16 + g;
                a[mi][0] = As[r * 36 + c];
                a[mi][1] = As[(r + 8) * 36 + c];
                a[mi][2] = As[r * 36 + c + 4];
                a[mi][3] = As[(r + 8) * 36 + c + 4];
            }
            unsigned b[4][2];
            #pragma unroll
            for (int ni = 0; ni < 4; ni++) {
                int nn = bcol + ni * 8 + g;
                b[ni][0] = Bs[c * 136 + nn];
                b[ni][1] = Bs[(c + 4) * 136 + nn];
            }
            #pragma unroll
            for (int mi = 0; mi < 4; mi++)
                #pragma unroll
                for (int ni = 0; ni < 4; ni++)
                    MMA_TF32(acc[mi][ni], a[mi], b[ni]);
        }
    }

    // epilogue: acc -> smem [128][132], pair G/U, write g_H (tf32-rounded)
    __syncthreads();
    float* Hs = (float*)sm;
    #pragma unroll
    for (int mi = 0; mi < 4; mi++) {
        int r1 = arow + mi * 16 + g, r2 = r1 + 8;
        #pragma unroll
        for (int ni = 0; ni < 4; ni++) {
            int cc = bcol + ni * 8 + 2 * tg;
            float* c = acc[mi][ni];
            *(float2*)(Hs + r1 * 132 + cc) = make_float2(c[0], c[1]);
            *(float2*)(Hs + r2 * 132 + cc) = make_float2(c[2], c[3]);
        }
    }
    __syncthreads();
    #pragma unroll
    for (int i = 0; i < 32; i++) {
        int e = tid + i * 256;
        int r = e >> 6, cc = e & 63;
        float gv = Hs[r * 132 + cc];
        float uv = Hs[r * 132 + 64 + cc];
        g_H[(size_t)(m0 + r) * IEXP + n0 + cc] = __uint_as_float(f2tf32(siluf(gv) * uv));
    }
}

// ======================================================================
// GEMM 2: out = cs*(H@Wd) + cx*x + cc0*c0 + cc1*c1
// CTA M=128 x N=128. 8 warps 2x4, warp tile m64xn32. K=8192, step 32.
// ======================================================================
__global__ __launch_bounds__(256, 2) void gemm_down(
    const float* __restrict__ X,
    const float* __restrict__ ceC,
    float* __restrict__ out)
{
    extern __shared__ unsigned sm[];
    const uint32_t sa = smem_u32(sm);
    const int tid = threadIdx.x;
    const int lane = tid & 31, wid = tid >> 5;
    const int wm = wid & 1, wn = wid >> 1;
    const int g = lane >> 2, tg = lane & 3;
    const int m0 = blockIdx.x * 128;
    const int n0 = blockIdx.y * 128;
    const int KT = IEXP / 32;

    float acc[4][4][4] = {};

    auto issue = [&](int kt) {
        int s = kt % 3, k0 = kt * 32;
        #pragma unroll
        for (int i = 0; i < 4; i++) {
            int e = tid + i * 256;
            int r = e >> 3, q = e & 7;
            cpa16(sa + (OFF_A(s) + r * 36 + q * 4) * 4,
                  g_H + (size_t)(m0 + r) * IEXP + k0 + q * 4);
        }
        #pragma unroll
        for (int i = 0; i < 4; i++) {
            int e = tid + i * 256;
            int kk = e >> 5, c8 = e & 31;
            cpa16(sa + (OFF_B(s) + kk * 136 + c8 * 4) * 4,
                  g_Wd32 + (size_t)(k0 + kk) * DHID + n0 + c8 * 4);
        }
        CPA_COMMIT();
    };

    issue(0); issue(1);
    const int arow = wm * 64;
    const int bcol = wn * 32;

    for (int kt = 0; kt < KT; kt++) {
        if (kt < KT - 1) CPA_WAIT(1); else CPA_WAIT(0);
        __syncthreads();
        if (kt + 2 < KT) issue(kt + 2);
        const unsigned* As = sm + OFF_A(kt % 3);
        const unsigned* Bs = sm + OFF_B(kt % 3);
        #pragma unroll
        for (int ks = 0; ks < 4; ks++) {
            int c = ks * 8 + tg;
            unsigned a[4][4];
            #pragma unroll
            for (int mi = 0; mi < 4; mi++) {
                int r = arow + mi * 16 + g;
                a[mi][0] = As[r * 36 + c];
                a[mi][1] = As[(r + 8) * 36 + c];
                a[mi][2] = As[r * 36 + c + 4];
                a[mi][3] = As[(r + 8) * 36 + c + 4];
            }
            unsigned b[4][2];
            #pragma unroll
            for (int ni = 0; ni < 4; ni++) {
                int nn = bcol + ni * 8 + g;
                b[ni][0] = Bs[c * 136 + nn];
                b[ni][1] = Bs[(c + 4) * 136 + nn];
            }
            #pragma unroll
            for (int mi = 0; mi < 4; mi++)
                #pragma unroll
                for (int ni = 0; ni < 4; ni++)
                    MMA_TF32(acc[mi][ni], a[mi], b[ni]);
        }
    }

    // epilogue: fold routing coefficients, direct from regs
    const float* c0 = ceC;
    const float* c1 = ceC + DHID;
    #pragma unroll
    for (int mi = 0; mi < 4; mi++) {
        int r1 = m0 + arow + mi * 16 + g;
        int r2 = r1 + 8;
        float cx1 = g_coef[r1 * 4 + 0], cc01 = g_coef[r1 * 4 + 1],
              cc11 = g_coef[r1 * 4 + 2], cs1 = g_coef[r1 * 4 + 3];
        float cx2 = g_coef[r2 * 4 + 0], cc02 = g_coef[r2 * 4 + 1],
              cc12 = g_coef[r2 * 4 + 2], cs2 = g_coef[r2 * 4 + 3];
        #pragma unroll
        for (int ni = 0; ni < 4; ni++) {
            int nn = n0 + bcol + ni * 8 + 2 * tg;
            float* c = acc[mi][ni];
            float2 x1 = *(const float2*)(X + (size_t)r1 * DHID + nn);
            float2 x2 = *(const float2*)(X + (size_t)r2 * DHID + nn);
            float2 v0 = *(const float2*)(c0 + nn);
            float2 v1 = *(const float2*)(c1 + nn);
            float2 o1, o2;
            o1.x = cs1 * c[0] + cx1 * x1.x + cc01 * v0.x + cc11 * v1.x;
            o1.y = cs1 * c[1] + cx1 * x1.y + cc01 * v0.y + cc11 * v1.y;
            o2.x = cs2 * c[2] + cx2 * x2.x + cc02 * v0.x + cc12 * v1.x;
            o2.y = cs2 * c[3] + cx2 * x2.y + cc02 * v0.y + cc12 * v1.y;
            *(float2*)(out + (size_t)r1 * DHID + nn) = o1;
            *(float2*)(out + (size_t)r2 * DHID + nn) = o2;
        }
    }
}

// ======================================================================
extern "C" void kernel_launch(void* const* d_in, const int* in_sizes, int n_in,
                              void* d_out, int out_size)
{
    const float* X    = (const float*)d_in[0];
    const float* W1   = (const float*)d_in[1];
    const float* W2   = (const float*)d_in[2];
    const float* ceWg = (const float*)d_in[3];
    const float* ceC  = (const float*)d_in[4];
    const float* Wg   = (const float*)d_in[5];
    const float* Wu   = (const float*)d_in[6];
    const float* Wd   = (const float*)d_in[7];
    float* out = (float*)d_out;
    float* logits = out + (size_t)NTOK * DHID;

    cudaFuncSetAttribute(gemm_gateup, cudaFuncAttributeMaxDynamicSharedMemorySize, SMEM_BYTES);
    cudaFuncSetAttribute(gemm_down, cudaFuncAttributeMaxDynamicSharedMemorySize, SMEM_BYTES);

    float *pX32, *pWg32, *pWu32, *pWd32;
    cudaGetSymbolAddress((void**)&pX32, g_X32);
    cudaGetSymbolAddress((void**)&pWg32, g_Wg32);
    cudaGetSymbolAddress((void**)&pWu32, g_Wu32);
    cudaGetSymbolAddress((void**)&pWd32, g_Wd32);

    // prep: tf32-round all GEMM operands once
    round_tf32_k<<<1024, 256>>>(X,  pX32,  NTOK * DHID / 4);
    round_tf32_k<<<2048, 256>>>(Wg, pWg32, DHID * IEXP / 4);
    round_tf32_k<<<2048, 256>>>(Wu, pWu32, DHID * IEXP / 4);
    round_tf32_k<<<2048, 256>>>(Wd, pWd32, IEXP * DHID / 4);

    // router
    router_gemm_tanh<<<NTOK / 64, 256>>>(X, W1);
    router_combine<<<NTOK, 128>>>(X, W2, ceWg, logits);

    // GEMMs
    gemm_gateup<<<dim3(NTOK / 128, IEXP / 64), 256, SMEM_BYTES>>>();
    gemm_down<<<dim3(NTOK / 128, DHID / 128), 256, SMEM_BYTES>>>(X, ceC, out);
}

// round 9
// speedup vs baseline: 1.6911x; 1.0584x over previous
#include <cuda_runtime.h>
#include <cstdint>

#define NTOK 4096
#define DHID 2048
#define IEXP 8192
#define NE   8
#define G1   64

// ---------------- scratch ----------------
__device__ float g_T[NTOK * G1];
__device__ float g_coef[NTOK * 4];
__device__ float g_X32[(size_t)NTOK * DHID];
__device__ float g_Wg32[(size_t)DHID * IEXP];
__device__ float g_Wu32[(size_t)DHID * IEXP];
__device__ float g_Wd32[(size_t)IEXP * DHID];
__device__ float g_H[(size_t)NTOK * IEXP];

// ---------------- helpers ----------------
__device__ __forceinline__ unsigned f2tf32(float x) {
    unsigned y; asm("cvt.rna.tf32.f32 %0, %1;" : "=r"(y) : "f"(x)); return y;
}
__device__ __forceinline__ float siluf(float z) { return z / (1.0f + __expf(-z)); }
__device__ __forceinline__ uint32_t smem_u32(const void* p) {
    uint32_t a;
    asm("{ .reg .u64 t; cvta.to.shared.u64 t, %1; cvt.u32.u64 %0, t; }" : "=r"(a) : "l"(p));
    return a;
}
__device__ __forceinline__ void cpa16(uint32_t d, const float* s) {
    asm volatile("cp.async.cg.shared.global [%0], [%1], 16;" :: "r"(d), "l"(s));
}
#define CPA_COMMIT() asm volatile("cp.async.commit_group;" ::: "memory")
#define CPA_WAIT(n)  asm volatile("cp.async.wait_group %0;" :: "n"(n) : "memory")

#define MMA_TF32(c, a, b)                                                        \
    asm volatile(                                                                \
        "mma.sync.aligned.m16n8k8.row.col.f32.tf32.tf32.f32 "                    \
        "{%0,%1,%2,%3}, {%4,%5,%6,%7}, {%8,%9}, {%0,%1,%2,%3};"                  \
        : "+f"((c)[0]), "+f"((c)[1]), "+f"((c)[2]), "+f"((c)[3])                 \
        : "r"((a)[0]), "r"((a)[1]), "r"((a)[2]), "r"((a)[3]),                    \
          "r"((b)[0]), "r"((b)[1]))

// per stage (floats): A 128x36 = 4608, B 32x136 = 4352 -> 8960
#define OFF_A(s) ((s) * 8960)
#define OFF_B(s) ((s) * 8960 + 4608)
#define SMEM_BYTES (3 * 8960 * 4)   // 107520 bytes -> 2 CTAs/SM

// ======================================================================
// Prep: elementwise tf32 rounding
// ======================================================================
__global__ __launch_bounds__(256) void round_tf32_k(
    const float* __restrict__ src, float* __restrict__ dst, int n4)
{
    int i = blockIdx.x * blockDim.x + threadIdx.x;
    int stride = gridDim.x * blockDim.x;
    for (; i < n4; i += stride) {
        float4 v = ((const float4*)src)[i];
        v.x = __uint_as_float(f2tf32(v.x)); v.y = __uint_as_float(f2tf32(v.y));
        v.z = __uint_as_float(f2tf32(v.z)); v.w = __uint_as_float(f2tf32(v.w));
        ((float4*)dst)[i] = v;
    }
}

// ======================================================================
// Router stage A: T = tanh(X @ gate_w1)
// ======================================================================
__global__ __launch_bounds__(256) void router_gemm_tanh(
    const float* __restrict__ X, const float* __restrict__ W1)
{
    __shared__ float Xs[32][65];
    __shared__ float Ws[32][64];
    const int tid = threadIdx.x;
    const int tx = tid & 15, ty = tid >> 4;
    const int m0 = blockIdx.x * 64;

    float acc[4][4] = {};
    for (int k0 = 0; k0 < DHID; k0 += 32) {
        __syncthreads();
        #pragma unroll
        for (int i = 0; i < 8; i++) {
            int e = tid + i * 256;
            Xs[e & 31][e >> 5] = X[(size_t)(m0 + (e >> 5)) * DHID + k0 + (e & 31)];
        }
        #pragma unroll
        for (int i = 0; i < 8; i++) {
            int e = tid + i * 256;
            Ws[e >> 6][e & 63] = W1[(size_t)(k0 + (e >> 6)) * G1 + (e & 63)];
        }
        __syncthreads();
        #pragma unroll
        for (int k = 0; k < 32; k++) {
            float av[4], bv[4];
            #pragma unroll
            for (int i = 0; i < 4; i++) av[i] = Xs[k][ty * 4 + i];
            #pragma unroll
            for (int j = 0; j < 4; j++) bv[j] = Ws[k][tx * 4 + j];
            #pragma unroll
            for (int i = 0; i < 4; i++)
                #pragma unroll
                for (int j = 0; j < 4; j++)
                    acc[i][j] = fmaf(av[i], bv[j], acc[i][j]);
        }
    }
    #pragma unroll
    for (int i = 0; i < 4; i++)
        #pragma unroll
        for (int j = 0; j < 4; j++)
            g_T[(size_t)(m0 + ty * 4 + i) * G1 + tx * 4 + j] = tanhf(acc[i][j]);
}

// ======================================================================
// Router stage B
// ======================================================================
__global__ __launch_bounds__(128) void router_combine(
    const float* __restrict__ X, const float* __restrict__ W2,
    const float* __restrict__ ceWg, float* __restrict__ logits_out)
{
    const int n = blockIdx.x;
    const int tid = threadIdx.x;
    __shared__ float red[4][128];
    __shared__ float lg[8];

    float pg0 = 0.f, pg1 = 0.f, pg2 = 0.f, pg3 = 0.f;
    for (int k = tid; k < DHID; k += 128) {
        float xv = X[(size_t)n * DHID + k];
        pg0 = fmaf(xv, ceWg[k * 2 + 0], pg0);
        pg1 = fmaf(xv, ceWg[k * 2 + 1], pg1);
        pg2 = fmaf(xv, ceWg[DHID * 2 + k * 2 + 0], pg2);
        pg3 = fmaf(xv, ceWg[DHID * 2 + k * 2 + 1], pg3);
    }
    red[0][tid] = pg0; red[1][tid] = pg1; red[2][tid] = pg2; red[3][tid] = pg3;
    __syncthreads();
    for (int s = 64; s > 0; s >>= 1) {
        if (tid < s) {
            #pragma unroll
            for (int j = 0; j < 4; j++) red[j][tid] += red[j][tid + s];
        }
        __syncthreads();
    }
    if (tid < NE) {
        float s = 0.f;
        #pragma unroll 8
        for (int i = 0; i < G1; i++)
            s = fmaf(g_T[(size_t)n * G1 + i], W2[i * NE + tid], s);
        lg[tid] = s;
        logits_out[(size_t)n * NE + tid] = s;
    }
    __syncthreads();
    if (tid == 0) {
        float p[NE];
        float mx = lg[0];
        #pragma unroll
        for (int e = 1; e < NE; e++) mx = fmaxf(mx, lg[e]);
        float sum = 0.f;
        #pragma unroll
        for (int e = 0; e < NE; e++) { p[e] = __expf(lg[e] - mx); sum += p[e]; }
        float inv = 1.f / sum;
        #pragma unroll
        for (int e = 0; e < NE; e++) p[e] *= inv;
        int i0 = 0;
        #pragma unroll
        for (int e = 1; e < NE; e++) if (p[e] > p[i0]) i0 = e;
        int i1 = (i0 == 0) ? 1 : 0;
        #pragma unroll
        for (int e = 0; e < NE; e++) if (e != i0 && p[e] > p[i1]) i1 = e;
        float w0 = (i0 == NE - 1) ? 0.f : p[i0];
        float w1 = (i1 == NE - 1) ? 0.f : p[i1];
        float winv = 1.f / (w0 + w1);
        w0 *= winv; w1 *= winv;
        float pe[NE];
        #pragma unroll
        for (int e = 0; e < NE; e++) pe[e] = 0.f;
        pe[i0] += w0; pe[i1] += w1;
        float cw0x = 1.f / (1.f + __expf(red[1][0] - red[0][0]));
        float cw1x = 1.f / (1.f + __expf(red[3][0] - red[2][0]));
        g_coef[n * 4 + 0] = pe[0] + pe[2] * cw0x + pe[3] * cw1x;
        g_coef[n * 4 + 1] = pe[2] * (1.f - cw0x);
        g_coef[n * 4 + 2] = pe[3] * (1.f - cw1x);
        g_coef[n * 4 + 3] = pe[4] + pe[5] + pe[6] + pe[7];
    }
}

// ======================================================================
// GEMM 1: H = silu(X@Wg) * (X@Wu)
// CTA: 128 threads (4 warps, 2x2), CTA tile M=128 x mmaN=128 (G|U 64 each).
// Warp tile m64 x n64. 3-stage cp.async, K step 32.
// ======================================================================
__global__ __launch_bounds__(128, 2) void gemm_gateup()
{
    extern __shared__ unsigned sm[];
    const uint32_t sa = smem_u32(sm);
    const int tid = threadIdx.x;
    const int lane = tid & 31, wid = tid >> 5;
    const int wm = wid & 1, wn = wid >> 1;          // 2x2
    const int g = lane >> 2, tg = lane & 3;
    const int m0 = blockIdx.x * 128;
    const int n0 = blockIdx.y * 64;
    const int KT = DHID / 32;

    float acc[4][8][4] = {};

    auto issue = [&](int kt) {
        int s = kt % 3, k0 = kt * 32;
        #pragma unroll
        for (int i = 0; i < 8; i++) {
            int e = tid + i * 128;
            int r = e >> 3, q = e & 7;
            cpa16(sa + (OFF_A(s) + r * 36 + q * 4) * 4,
                  g_X32 + (size_t)(m0 + r) * DHID + k0 + q * 4);
        }
        #pragma unroll
        for (int i = 0; i < 8; i++) {
            int e = tid + i * 128;
            int kk = e >> 5, c8 = e & 31;
            const float* src = (c8 < 16)
                ? g_Wg32 + (size_t)(k0 + kk) * IEXP + n0 + c8 * 4
                : g_Wu32 + (size_t)(k0 + kk) * IEXP + n0 + (c8 - 16) * 4;
            cpa16(sa + (OFF_B(s) + kk * 136 + c8 * 4) * 4, src);
        }
        CPA_COMMIT();
    };

    issue(0); issue(1);
    const int arow = wm * 64;
    const int bcol = wn * 64;

    for (int kt = 0; kt < KT; kt++) {
        if (kt < KT - 1) CPA_WAIT(1); else CPA_WAIT(0);
        __syncthreads();
        if (kt + 2 < KT) issue(kt + 2);
        const unsigned* As = sm + OFF_A(kt % 3);
        const unsigned* Bs = sm + OFF_B(kt % 3);
        #pragma unroll
        for (int ks = 0; ks < 4; ks++) {
            int c = ks * 8 + tg;
            unsigned a[4][4];
            #pragma unroll
            for (int mi = 0; mi < 4; mi++) {
                int r = arow + mi * 16 + g;
                a[mi][0] = As[r * 36 + c];
                a[mi][1] = As[(r + 8) * 36 + c];
                a[mi][2] = As[r * 36 + c + 4];
                a[mi][3] = As[(r + 8) * 36 + c + 4];
            }
            unsigned b[8][2];
            #pragma unroll
            for (int ni = 0; ni < 8; ni++) {
                int nn = bcol + ni * 8 + g;
                b[ni][0] = Bs[c * 136 + nn];
                b[ni][1] = Bs[(c + 4) * 136 + nn];
            }
            #pragma unroll
            for (int mi = 0; mi < 4; mi++)
                #pragma unroll
                for (int ni = 0; ni < 8; ni++)
                    MMA_TF32(acc[mi][ni], a[mi], b[ni]);
        }
    }

    // epilogue: acc -> smem [128][132], pair G/U, write g_H (tf32-rounded)
    __syncthreads();
    float* Hs = (float*)sm;
    #pragma unroll
    for (int mi = 0; mi < 4; mi++) {
        int r1 = arow + mi * 16 + g, r2 = r1 + 8;
        #pragma unroll
        for (int ni = 0; ni < 8; ni++) {
            int cc = bcol + ni * 8 + 2 * tg;
            float* c = acc[mi][ni];
            *(float2*)(Hs + r1 * 132 + cc) = make_float2(c[0], c[1]);
            *(float2*)(Hs + r2 * 132 + cc) = make_float2(c[2], c[3]);
        }
    }
    __syncthreads();
    #pragma unroll
    for (int i = 0; i < 64; i++) {
        int e = tid + i * 128;
        int r = e >> 6, cc = e & 63;
        float gv = Hs[r * 132 + cc];
        float uv = Hs[r * 132 + 64 + cc];
        g_H[(size_t)(m0 + r) * IEXP + n0 + cc] = __uint_as_float(f2tf32(siluf(gv) * uv));
    }
}

// ======================================================================
// GEMM 2: out = cs*(H@Wd) + cx*x + cc0*c0 + cc1*c1
// CTA: 128 threads (4 warps, 2x2), tile M=128 x N=128. Warp tile m64xn64.
// ======================================================================
__global__ __launch_bounds__(128, 2) void gemm_down(
    const float* __restrict__ X,
    const float* __restrict__ ceC,
    float* __restrict__ out)
{
    extern __shared__ unsigned sm[];
    const uint32_t sa = smem_u32(sm);
    const int tid = threadIdx.x;
    const int lane = tid & 31, wid = tid >> 5;
    const int wm = wid & 1, wn = wid >> 1;
    const int g = lane >> 2, tg = lane & 3;
    const int m0 = blockIdx.x * 128;
    const int n0 = blockIdx.y * 128;
    const int KT = IEXP / 32;

    float acc[4][8][4] = {};

    auto issue = [&](int kt) {
        int s = kt % 3, k0 = kt * 32;
        #pragma unroll
        for (int i = 0; i < 8; i++) {
            int e = tid + i * 128;
            int r = e >> 3, q = e & 7;
            cpa16(sa + (OFF_A(s) + r * 36 + q * 4) * 4,
                  g_H + (size_t)(m0 + r) * IEXP + k0 + q * 4);
        }
        #pragma unroll
        for (int i = 0; i < 8; i++) {
            int e = tid + i * 128;
            int kk = e >> 5, c8 = e & 31;
            cpa16(sa + (OFF_B(s) + kk * 136 + c8 * 4) * 4,
                  g_Wd32 + (size_t)(k0 + kk) * DHID + n0 + c8 * 4);
        }
        CPA_COMMIT();
    };

    issue(0); issue(1);
    const int arow = wm * 64;
    const int bcol = wn * 64;

    for (int kt = 0; kt < KT; kt++) {
        if (kt < KT - 1) CPA_WAIT(1); else CPA_WAIT(0);
        __syncthreads();
        if (kt + 2 < KT) issue(kt + 2);
        const unsigned* As = sm + OFF_A(kt % 3);
        const unsigned* Bs = sm + OFF_B(kt % 3);
        #pragma unroll
        for (int ks = 0; ks < 4; ks++) {
            int c = ks * 8 + tg;
            unsigned a[4][4];
            #pragma unroll
            for (int mi = 0; mi < 4; mi++) {
                int r = arow + mi * 16 + g;
                a[mi][0] = As[r * 36 + c];
                a[mi][1] = As[(r + 8) * 36 + c];
                a[mi][2] = As[r * 36 + c + 4];
                a[mi][3] = As[(r + 8) * 36 + c + 4];
            }
            unsigned b[8][2];
            #pragma unroll
            for (int ni = 0; ni < 8; ni++) {
                int nn = bcol + ni * 8 + g;
                b[ni][0] = Bs[c * 136 + nn];
                b[ni][1] = Bs[(c + 4) * 136 + nn];
            }
            #pragma unroll
            for (int mi = 0; mi < 4; mi++)
                #pragma unroll
                for (int ni = 0; ni < 8; ni++)
                    MMA_TF32(acc[mi][ni], a[mi], b[ni]);
        }
    }

    // epilogue: fold routing coefficients, direct from regs
    const float* c0 = ceC;
    const float* c1 = ceC + DHID;
    #pragma unroll
    for (int mi = 0; mi < 4; mi++) {
        int r1 = m0 + arow + mi * 16 + g;
        int r2 = r1 + 8;
        float cx1 = g_coef[r1 * 4 + 0], cc01 = g_coef[r1 * 4 + 1],
              cc11 = g_coef[r1 * 4 + 2], cs1 = g_coef[r1 * 4 + 3];
        float cx2 = g_coef[r2 * 4 + 0], cc02 = g_coef[r2 * 4 + 1],
              cc12 = g_coef[r2 * 4 + 2], cs2 = g_coef[r2 * 4 + 3];
        #pragma unroll
        for (int ni = 0; ni < 8; ni++) {
            int nn = n0 + bcol + ni * 8 + 2 * tg;
            float* c = acc[mi][ni];
            float2 x1 = *(const float2*)(X + (size_t)r1 * DHID + nn);
            float2 x2 = *(const float2*)(X + (size_t)r2 * DHID + nn);
            float2 v0 = *(const float2*)(c0 + nn);
            float2 v1 = *(const float2*)(c1 + nn);
            float2 o1, o2;
            o1.x = cs1 * c[0] + cx1 * x1.x + cc01 * v0.x + cc11 * v1.x;
            o1.y = cs1 * c[1] + cx1 * x1.y + cc01 * v0.y + cc11 * v1.y;
            o2.x = cs2 * c[2] + cx2 * x2.x + cc02 * v0.x + cc12 * v1.x;
            o2.y = cs2 * c[3] + cx2 * x2.y + cc02 * v0.y + cc12 * v1.y;
            *(float2*)(out + (size_t)r1 * DHID + nn) = o1;
            *(float2*)(out + (size_t)r2 * DHID + nn) = o2;
        }
    }
}

// ======================================================================
extern "C" void kernel_launch(void* const* d_in, const int* in_sizes, int n_in,
                              void* d_out, int out_size)
{
    const float* X    = (const float*)d_in[0];
    const float* W1   = (const float*)d_in[1];
    const float* W2   = (const float*)d_in[2];
    const float* ceWg = (const float*)d_in[3];
    const float* ceC  = (const float*)d_in[4];
    const float* Wg   = (const float*)d_in[5];
    const float* Wu   = (const float*)d_in[6];
    const float* Wd   = (const float*)d_in[7];
    float* out = (float*)d_out;
    float* logits = out + (size_t)NTOK * DHID;

    cudaFuncSetAttribute(gemm_gateup, cudaFuncAttributeMaxDynamicSharedMemorySize, SMEM_BYTES);
    cudaFuncSetAttribute(gemm_down, cudaFuncAttributeMaxDynamicSharedMemorySize, SMEM_BYTES);

    float *pX32, *pWg32, *pWu32, *pWd32;
    cudaGetSymbolAddress((void**)&pX32, g_X32);
    cudaGetSymbolAddress((void**)&pWg32, g_Wg32);
    cudaGetSymbolAddress((void**)&pWu32, g_Wu32);
    cudaGetSymbolAddress((void**)&pWd32, g_Wd32);

    // prep: tf32-round all GEMM operands once
    round_tf32_k<<<1024, 256>>>(X,  pX32,  NTOK * DHID / 4);
    round_tf32_k<<<2048, 256>>>(Wg, pWg32, DHID * IEXP / 4);
    round_tf32_k<<<2048, 256>>>(Wu, pWu32, DHID * IEXP / 4);
    round_tf32_k<<<2048, 256>>>(Wd, pWd32, IEXP * DHID / 4);

    // router
    router_gemm_tanh<<<NTOK / 64, 256>>>(X, W1);
    router_combine<<<NTOK, 128>>>(X, W2, ceWg, logits);

    // GEMMs
    gemm_gateup<<<dim3(NTOK / 128, IEXP / 64), 128, SMEM_BYTES>>>();
    gemm_down<<<dim3(NTOK / 128, DHID / 128), 128, SMEM_BYTES>>>(X, ceC, out);
}

// round 10
// speedup vs baseline: 1.8242x; 1.0787x over previous
#include <cuda_runtime.h>
#include <cstdint>

#define NTOK 4096
#define DHID 2048
#define IEXP 8192
#define NE   8
#define G1   64

// ---------------- scratch ----------------
__device__ float g_T[NTOK * G1];
__device__ float g_coef[NTOK * 4];
__device__ float g_X32[(size_t)NTOK * DHID];
__device__ float g_Wg32[(size_t)DHID * IEXP];
__device__ float g_Wu32[(size_t)DHID * IEXP];
__device__ float g_Wd32[(size_t)IEXP * DHID];
__device__ float g_H[(size_t)NTOK * IEXP];

// ---------------- helpers ----------------
__device__ __forceinline__ unsigned f2tf32(float x) {
    unsigned y; asm("cvt.rna.tf32.f32 %0, %1;" : "=r"(y) : "f"(x)); return y;
}
__device__ __forceinline__ float siluf(float z) { return z / (1.0f + __expf(-z)); }
__device__ __forceinline__ uint32_t smem_u32(const void* p) {
    uint32_t a;
    asm("{ .reg .u64 t; cvta.to.shared.u64 t, %1; cvt.u32.u64 %0, t; }" : "=r"(a) : "l"(p));
    return a;
}
__device__ __forceinline__ void cpa16(uint32_t d, const float* s) {
    asm volatile("cp.async.cg.shared.global [%0], [%1], 16;" :: "r"(d), "l"(s));
}
#define CPA_COMMIT() asm volatile("cp.async.commit_group;" ::: "memory")
#define CPA_WAIT(n)  asm volatile("cp.async.wait_group %0;" :: "n"(n) : "memory")

#define MMA_TF32(c, a, b)                                                        \
    asm volatile(                                                                \
        "mma.sync.aligned.m16n8k8.row.col.f32.tf32.tf32.f32 "                    \
        "{%0,%1,%2,%3}, {%4,%5,%6,%7}, {%8,%9}, {%0,%1,%2,%3};"                  \
        : "+f"((c)[0]), "+f"((c)[1]), "+f"((c)[2]), "+f"((c)[3])                 \
        : "r"((a)[0]), "r"((a)[1]), "r"((a)[2]), "r"((a)[3]),                    \
          "r"((b)[0]), "r"((b)[1]))

// per stage (floats): A 128x36 = 4608, B 32x136 = 4352 -> 8960
#define OFF_A(s) ((s) * 8960)
#define OFF_B(s) ((s) * 8960 + 4608)
#define SMEM_BYTES (2 * 8960 * 4)   // 71680 bytes, 2 stages -> 3 CTAs/SM

// ======================================================================
// Prep: elementwise tf32 rounding
// ======================================================================
__global__ __launch_bounds__(256) void round_tf32_k(
    const float* __restrict__ src, float* __restrict__ dst, int n4)
{
    int i = blockIdx.x * blockDim.x + threadIdx.x;
    int stride = gridDim.x * blockDim.x;
    for (; i < n4; i += stride) {
        float4 v = ((const float4*)src)[i];
        v.x = __uint_as_float(f2tf32(v.x)); v.y = __uint_as_float(f2tf32(v.y));
        v.z = __uint_as_float(f2tf32(v.z)); v.w = __uint_as_float(f2tf32(v.w));
        ((float4*)dst)[i] = v;
    }
}

// ======================================================================
// Router stage A: T = tanh(X @ gate_w1)
// ======================================================================
__global__ __launch_bounds__(256) void router_gemm_tanh(
    const float* __restrict__ X, const float* __restrict__ W1)
{
    __shared__ float Xs[32][65];
    __shared__ float Ws[32][64];
    const int tid = threadIdx.x;
    const int tx = tid & 15, ty = tid >> 4;
    const int m0 = blockIdx.x * 64;

    float acc[4][4] = {};
    for (int k0 = 0; k0 < DHID; k0 += 32) {
        __syncthreads();
        #pragma unroll
        for (int i = 0; i < 8; i++) {
            int e = tid + i * 256;
            Xs[e & 31][e >> 5] = X[(size_t)(m0 + (e >> 5)) * DHID + k0 + (e & 31)];
        }
        #pragma unroll
        for (int i = 0; i < 8; i++) {
            int e = tid + i * 256;
            Ws[e >> 6][e & 63] = W1[(size_t)(k0 + (e >> 6)) * G1 + (e & 63)];
        }
        __syncthreads();
        #pragma unroll
        for (int k = 0; k < 32; k++) {
            float av[4], bv[4];
            #pragma unroll
            for (int i = 0; i < 4; i++) av[i] = Xs[k][ty * 4 + i];
            #pragma unroll
            for (int j = 0; j < 4; j++) bv[j] = Ws[k][tx * 4 + j];
            #pragma unroll
            for (int i = 0; i < 4; i++)
                #pragma unroll
                for (int j = 0; j < 4; j++)
                    acc[i][j] = fmaf(av[i], bv[j], acc[i][j]);
        }
    }
    #pragma unroll
    for (int i = 0; i < 4; i++)
        #pragma unroll
        for (int j = 0; j < 4; j++)
            g_T[(size_t)(m0 + ty * 4 + i) * G1 + tx * 4 + j] = tanhf(acc[i][j]);
}

// ======================================================================
// Router stage B
// ======================================================================
__global__ __launch_bounds__(128) void router_combine(
    const float* __restrict__ X, const float* __restrict__ W2,
    const float* __restrict__ ceWg, float* __restrict__ logits_out)
{
    const int n = blockIdx.x;
    const int tid = threadIdx.x;
    __shared__ float red[4][128];
    __shared__ float lg[8];

    float pg0 = 0.f, pg1 = 0.f, pg2 = 0.f, pg3 = 0.f;
    for (int k = tid; k < DHID; k += 128) {
        float xv = X[(size_t)n * DHID + k];
        pg0 = fmaf(xv, ceWg[k * 2 + 0], pg0);
        pg1 = fmaf(xv, ceWg[k * 2 + 1], pg1);
        pg2 = fmaf(xv, ceWg[DHID * 2 + k * 2 + 0], pg2);
        pg3 = fmaf(xv, ceWg[DHID * 2 + k * 2 + 1], pg3);
    }
    red[0][tid] = pg0; red[1][tid] = pg1; red[2][tid] = pg2; red[3][tid] = pg3;
    __syncthreads();
    for (int s = 64; s > 0; s >>= 1) {
        if (tid < s) {
            #pragma unroll
            for (int j = 0; j < 4; j++) red[j][tid] += red[j][tid + s];
        }
        __syncthreads();
    }
    if (tid < NE) {
        float s = 0.f;
        #pragma unroll 8
        for (int i = 0; i < G1; i++)
            s = fmaf(g_T[(size_t)n * G1 + i], W2[i * NE + tid], s);
        lg[tid] = s;
        logits_out[(size_t)n * NE + tid] = s;
    }
    __syncthreads();
    if (tid == 0) {
        float p[NE];
        float mx = lg[0];
        #pragma unroll
        for (int e = 1; e < NE; e++) mx = fmaxf(mx, lg[e]);
        float sum = 0.f;
        #pragma unroll
        for (int e = 0; e < NE; e++) { p[e] = __expf(lg[e] - mx); sum += p[e]; }
        float inv = 1.f / sum;
        #pragma unroll
        for (int e = 0; e < NE; e++) p[e] *= inv;
        int i0 = 0;
        #pragma unroll
        for (int e = 1; e < NE; e++) if (p[e] > p[i0]) i0 = e;
        int i1 = (i0 == 0) ? 1 : 0;
        #pragma unroll
        for (int e = 0; e < NE; e++) if (e != i0 && p[e] > p[i1]) i1 = e;
        float w0 = (i0 == NE - 1) ? 0.f : p[i0];
        float w1 = (i1 == NE - 1) ? 0.f : p[i1];
        float winv = 1.f / (w0 + w1);
        w0 *= winv; w1 *= winv;
        float pe[NE];
        #pragma unroll
        for (int e = 0; e < NE; e++) pe[e] = 0.f;
        pe[i0] += w0; pe[i1] += w1;
        float cw0x = 1.f / (1.f + __expf(red[1][0] - red[0][0]));
        float cw1x = 1.f / (1.f + __expf(red[3][0] - red[2][0]));
        g_coef[n * 4 + 0] = pe[0] + pe[2] * cw0x + pe[3] * cw1x;
        g_coef[n * 4 + 1] = pe[2] * (1.f - cw0x);
        g_coef[n * 4 + 2] = pe[3] * (1.f - cw1x);
        g_coef[n * 4 + 3] = pe[4] + pe[5] + pe[6] + pe[7];
    }
}

// ======================================================================
// GEMM 1: H = silu(X@Wg) * (X@Wu)
// CTA: 128 threads (4 warps, 2x2), CTA tile M=128 x mmaN=128 (G|U 64 each).
// Warp tile m64 x n64. 2-stage cp.async, K step 32, 3 CTAs/SM.
// ======================================================================
__global__ __launch_bounds__(128, 3) void gemm_gateup()
{
    extern __shared__ unsigned sm[];
    const uint32_t sa = smem_u32(sm);
    const int tid = threadIdx.x;
    const int lane = tid & 31, wid = tid >> 5;
    const int wm = wid & 1, wn = wid >> 1;          // 2x2
    const int g = lane >> 2, tg = lane & 3;
    const int m0 = blockIdx.x * 128;
    const int n0 = blockIdx.y * 64;
    const int KT = DHID / 32;

    float acc[4][8][4] = {};

    auto issue = [&](int kt) {
        int s = kt & 1, k0 = kt * 32;
        #pragma unroll
        for (int i = 0; i < 8; i++) {
            int e = tid + i * 128;
            int r = e >> 3, q = e & 7;
            cpa16(sa + (OFF_A(s) + r * 36 + q * 4) * 4,
                  g_X32 + (size_t)(m0 + r) * DHID + k0 + q * 4);
        }
        #pragma unroll
        for (int i = 0; i < 8; i++) {
            int e = tid + i * 128;
            int kk = e >> 5, c8 = e & 31;
            const float* src = (c8 < 16)
                ? g_Wg32 + (size_t)(k0 + kk) * IEXP + n0 + c8 * 4
                : g_Wu32 + (size_t)(k0 + kk) * IEXP + n0 + (c8 - 16) * 4;
            cpa16(sa + (OFF_B(s) + kk * 136 + c8 * 4) * 4, src);
        }
        CPA_COMMIT();
    };

    issue(0);
    const int arow = wm * 64;
    const int bcol = wn * 64;

    for (int kt = 0; kt < KT; kt++) {
        CPA_WAIT(0);
        __syncthreads();
        if (kt + 1 < KT) issue(kt + 1);
        const unsigned* As = sm + OFF_A(kt & 1);
        const unsigned* Bs = sm + OFF_B(kt & 1);
        #pragma unroll
        for (int ks = 0; ks < 4; ks++) {
            int c = ks * 8 + tg;
            unsigned a[4][4];
            #pragma unroll
            for (int mi = 0; mi < 4; mi++) {
                int r = arow + mi * 16 + g;
                a[mi][0] = As[r * 36 + c];
                a[mi][1] = As[(r + 8) * 36 + c];
                a[mi][2] = As[r * 36 + c + 4];
                a[mi][3] = As[(r + 8) * 36 + c + 4];
            }
            unsigned b[8][2];
            #pragma unroll
            for (int ni = 0; ni < 8; ni++) {
                int nn = bcol + ni * 8 + g;
                b[ni][0] = Bs[c * 136 + nn];
                b[ni][1] = Bs[(c + 4) * 136 + nn];
            }
            #pragma unroll
            for (int mi = 0; mi < 4; mi++)
                #pragma unroll
                for (int ni = 0; ni < 8; ni++)
                    MMA_TF32(acc[mi][ni], a[mi], b[ni]);
        }
        __syncthreads();
    }

    // epilogue: acc -> smem [128][132], pair G/U, write g_H (tf32-rounded)
    float* Hs = (float*)sm;
    #pragma unroll
    for (int mi = 0; mi < 4; mi++) {
        int r1 = arow + mi * 16 + g, r2 = r1 + 8;
        #pragma unroll
        for (int ni = 0; ni < 8; ni++) {
            int cc = bcol + ni * 8 + 2 * tg;
            float* c = acc[mi][ni];
            *(float2*)(Hs + r1 * 132 + cc) = make_float2(c[0], c[1]);
            *(float2*)(Hs + r2 * 132 + cc) = make_float2(c[2], c[3]);
        }
    }
    __syncthreads();
    #pragma unroll
    for (int i = 0; i < 64; i++) {
        int e = tid + i * 128;
        int r = e >> 6, cc = e & 63;
        float gv = Hs[r * 132 + cc];
        float uv = Hs[r * 132 + 64 + cc];
        g_H[(size_t)(m0 + r) * IEXP + n0 + cc] = __uint_as_float(f2tf32(siluf(gv) * uv));
    }
}

// ======================================================================
// GEMM 2: out = cs*(H@Wd) + cx*x + cc0*c0 + cc1*c1
// CTA: 128 threads (4 warps, 2x2), tile M=128 x N=128. Warp tile m64xn64.
// 2-stage cp.async, 3 CTAs/SM.
// ======================================================================
__global__ __launch_bounds__(128, 3) void gemm_down(
    const float* __restrict__ X,
    const float* __restrict__ ceC,
    float* __restrict__ out)
{
    extern __shared__ unsigned sm[];
    const uint32_t sa = smem_u32(sm);
    const int tid = threadIdx.x;
    const int lane = tid & 31, wid = tid >> 5;
    const int wm = wid & 1, wn = wid >> 1;
    const int g = lane >> 2, tg = lane & 3;
    const int m0 = blockIdx.x * 128;
    const int n0 = blockIdx.y * 128;
    const int KT = IEXP / 32;

    float acc[4][8][4] = {};

    auto issue = [&](int kt) {
        int s = kt & 1, k0 = kt * 32;
        #pragma unroll
        for (int i = 0; i < 8; i++) {
            int e = tid + i * 128;
            int r = e >> 3, q = e & 7;
            cpa16(sa + (OFF_A(s) + r * 36 + q * 4) * 4,
                  g_H + (size_t)(m0 + r) * IEXP + k0 + q * 4);
        }
        #pragma unroll
        for (int i = 0; i < 8; i++) {
            int e = tid + i * 128;
            int kk = e >> 5, c8 = e & 31;
            cpa16(sa + (OFF_B(s) + kk * 136 + c8 * 4) * 4,
                  g_Wd32 + (size_t)(k0 + kk) * DHID + n0 + c8 * 4);
        }
        CPA_COMMIT();
    };

    issue(0);
    const int arow = wm * 64;
    const int bcol = wn * 64;

    for (int kt = 0; kt < KT; kt++) {
        CPA_WAIT(0);
        __syncthreads();
        if (kt + 1 < KT) issue(kt + 1);
        const unsigned* As = sm + OFF_A(kt & 1);
        const unsigned* Bs = sm + OFF_B(kt & 1);
        #pragma unroll
        for (int ks = 0; ks < 4; ks++) {
            int c = ks * 8 + tg;
            unsigned a[4][4];
            #pragma unroll
            for (int mi = 0; mi < 4; mi++) {
                int r = arow + mi * 16 + g;
                a[mi][0] = As[r * 36 + c];
                a[mi][1] = As[(r + 8) * 36 + c];
                a[mi][2] = As[r * 36 + c + 4];
                a[mi][3] = As[(r + 8) * 36 + c + 4];
            }
            unsigned b[8][2];
            #pragma unroll
            for (int ni = 0; ni < 8; ni++) {
                int nn = bcol + ni * 8 + g;
                b[ni][0] = Bs[c * 136 + nn];
                b[ni][1] = Bs[(c + 4) * 136 + nn];
            }
            #pragma unroll
            for (int mi = 0; mi < 4; mi++)
                #pragma unroll
                for (int ni = 0; ni < 8; ni++)
                    MMA_TF32(acc[mi][ni], a[mi], b[ni]);
        }
        __syncthreads();
    }

    // epilogue: fold routing coefficients, direct from regs
    const float* c0 = ceC;
    const float* c1 = ceC + DHID;
    #pragma unroll
    for (int mi = 0; mi < 4; mi++) {
        int r1 = m0 + arow + mi * 16 + g;
        int r2 = r1 + 8;
        float cx1 = g_coef[r1 * 4 + 0], cc01 = g_coef[r1 * 4 + 1],
              cc11 = g_coef[r1 * 4 + 2], cs1 = g_coef[r1 * 4 + 3];
        float cx2 = g_coef[r2 * 4 + 0], cc02 = g_coef[r2 * 4 + 1],
              cc12 = g_coef[r2 * 4 + 2], cs2 = g_coef[r2 * 4 + 3];
        #pragma unroll
        for (int ni = 0; ni < 8; ni++) {
            int nn = n0 + bcol + ni * 8 + 2 * tg;
            float* c = acc[mi][ni];
            float2 x1 = *(const float2*)(X + (size_t)r1 * DHID + nn);
            float2 x2 = *(const float2*)(X + (size_t)r2 * DHID + nn);
            float2 v0 = *(const float2*)(c0 + nn);
            float2 v1 = *(const float2*)(c1 + nn);
            float2 o1, o2;
            o1.x = cs1 * c[0] + cx1 * x1.x + cc01 * v0.x + cc11 * v1.x;
            o1.y = cs1 * c[1] + cx1 * x1.y + cc01 * v0.y + cc11 * v1.y;
            o2.x = cs2 * c[2] + cx2 * x2.x + cc02 * v0.x + cc12 * v1.x;
            o2.y = cs2 * c[3] + cx2 * x2.y + cc02 * v0.y + cc12 * v1.y;
            *(float2*)(out + (size_t)r1 * DHID + nn) = o1;
            *(float2*)(out + (size_t)r2 * DHID + nn) = o2;
        }
    }
}

// ======================================================================
extern "C" void kernel_launch(void* const* d_in, const int* in_sizes, int n_in,
                              void* d_out, int out_size)
{
    const float* X    = (const float*)d_in[0];
    const float* W1   = (const float*)d_in[1];
    const float* W2   = (const float*)d_in[2];
    const float* ceWg = (const float*)d_in[3];
    const float* ceC  = (const float*)d_in[4];
    const float* Wg   = (const float*)d_in[5];
    const float* Wu   = (const float*)d_in[6];
    const float* Wd   = (const float*)d_in[7];
    float* out = (float*)d_out;
    float* logits = out + (size_t)NTOK * DHID;

    cudaFuncSetAttribute(gemm_gateup, cudaFuncAttributeMaxDynamicSharedMemorySize, SMEM_BYTES);
    cudaFuncSetAttribute(gemm_down, cudaFuncAttributeMaxDynamicSharedMemorySize, SMEM_BYTES);

    float *pX32, *pWg32, *pWu32, *pWd32;
    cudaGetSymbolAddress((void**)&pX32, g_X32);
    cudaGetSymbolAddress((void**)&pWg32, g_Wg32);
    cudaGetSymbolAddress((void**)&pWu32, g_Wu32);
    cudaGetSymbolAddress((void**)&pWd32, g_Wd32);

    // prep: tf32-round all GEMM operands once
    round_tf32_k<<<1024, 256>>>(X,  pX32,  NTOK * DHID / 4);
    round_tf32_k<<<2048, 256>>>(Wg, pWg32, DHID * IEXP / 4);
    round_tf32_k<<<2048, 256>>>(Wu, pWu32, DHID * IEXP / 4);
    round_tf32_k<<<2048, 256>>>(Wd, pWd32, IEXP * DHID / 4);

    // router
    router_gemm_tanh<<<NTOK / 64, 256>>>(X, W1);
    router_combine<<<NTOK, 128>>>(X, W2, ceWg, logits);

    // GEMMs
    gemm_gateup<<<dim3(NTOK / 128, IEXP / 64), 128, SMEM_BYTES>>>();
    gemm_down<<<dim3(NTOK / 128, DHID / 128), 128, SMEM_BYTES>>>(X, ceC, out);
}

// round 11
// speedup vs baseline: 1.8295x; 1.0029x over previous
#include <cuda_runtime.h>
#include <cstdint>

#define NTOK 4096
#define DHID 2048
#define IEXP 8192
#define NE   8
#define G1   64

// ---------------- scratch ----------------
__device__ float g_T[NTOK * G1];
__device__ float g_coef[NTOK * 4];
__device__ float g_X32[(size_t)NTOK * DHID];
__device__ float g_Wg32[(size_t)DHID * IEXP];
__device__ float g_Wu32[(size_t)DHID * IEXP];
__device__ float g_Wd32[(size_t)IEXP * DHID];
__device__ float g_H[(size_t)NTOK * IEXP];

// ---------------- helpers ----------------
__device__ __forceinline__ unsigned f2tf32(float x) {
    unsigned y; asm("cvt.rna.tf32.f32 %0, %1;" : "=r"(y) : "f"(x)); return y;
}
__device__ __forceinline__ float siluf(float z) { return z / (1.0f + __expf(-z)); }
__device__ __forceinline__ uint32_t smem_u32(const void* p) {
    uint32_t a;
    asm("{ .reg .u64 t; cvta.to.shared.u64 t, %1; cvt.u32.u64 %0, t; }" : "=r"(a) : "l"(p));
    return a;
}
__device__ __forceinline__ void cpa16(uint32_t d, const float* s) {
    asm volatile("cp.async.cg.shared.global [%0], [%1], 16;" :: "r"(d), "l"(s));
}
#define CPA_COMMIT() asm volatile("cp.async.commit_group;" ::: "memory")
#define CPA_WAIT(n)  asm volatile("cp.async.wait_group %0;" :: "n"(n) : "memory")

#define MMA_TF32(c, a, b)                                                        \
    asm volatile(                                                                \
        "mma.sync.aligned.m16n8k8.row.col.f32.tf32.tf32.f32 "                    \
        "{%0,%1,%2,%3}, {%4,%5,%6,%7}, {%8,%9}, {%0,%1,%2,%3};"                  \
        : "+f"((c)[0]), "+f"((c)[1]), "+f"((c)[2]), "+f"((c)[3])                 \
        : "r"((a)[0]), "r"((a)[1]), "r"((a)[2]), "r"((a)[3]),                    \
          "r"((b)[0]), "r"((b)[1]))

// per stage (floats): A 128x36 = 4608, B 32x136 = 4352 -> 8960
#define OFF_A(s) ((s) * 8960)
#define OFF_B(s) ((s) * 8960 + 4608)
#define SMEM_BYTES (2 * 8960 * 4)   // 71680 bytes, 2 stages -> 3 CTAs/SM

// ======================================================================
// Prep: elementwise tf32 rounding
// ======================================================================
__global__ __launch_bounds__(256) void round_tf32_k(
    const float* __restrict__ src, float* __restrict__ dst, int n4)
{
    int i = blockIdx.x * blockDim.x + threadIdx.x;
    int stride = gridDim.x * blockDim.x;
    for (; i < n4; i += stride) {
        float4 v = ((const float4*)src)[i];
        v.x = __uint_as_float(f2tf32(v.x)); v.y = __uint_as_float(f2tf32(v.y));
        v.z = __uint_as_float(f2tf32(v.z)); v.w = __uint_as_float(f2tf32(v.w));
        ((float4*)dst)[i] = v;
    }
}

// ======================================================================
// Router stage A: T = tanh(X @ gate_w1)
// ======================================================================
__global__ __launch_bounds__(256) void router_gemm_tanh(
    const float* __restrict__ X, const float* __restrict__ W1)
{
    __shared__ float Xs[32][65];
    __shared__ float Ws[32][64];
    const int tid = threadIdx.x;
    const int tx = tid & 15, ty = tid >> 4;
    const int m0 = blockIdx.x * 64;

    float acc[4][4] = {};
    for (int k0 = 0; k0 < DHID; k0 += 32) {
        __syncthreads();
        #pragma unroll
        for (int i = 0; i < 8; i++) {
            int e = tid + i * 256;
            Xs[e & 31][e >> 5] = X[(size_t)(m0 + (e >> 5)) * DHID + k0 + (e & 31)];
        }
        #pragma unroll
        for (int i = 0; i < 8; i++) {
            int e = tid + i * 256;
            Ws[e >> 6][e & 63] = W1[(size_t)(k0 + (e >> 6)) * G1 + (e & 63)];
        }
        __syncthreads();
        #pragma unroll
        for (int k = 0; k < 32; k++) {
            float av[4], bv[4];
            #pragma unroll
            for (int i = 0; i < 4; i++) av[i] = Xs[k][ty * 4 + i];
            #pragma unroll
            for (int j = 0; j < 4; j++) bv[j] = Ws[k][tx * 4 + j];
            #pragma unroll
            for (int i = 0; i < 4; i++)
                #pragma unroll
                for (int j = 0; j < 4; j++)
                    acc[i][j] = fmaf(av[i], bv[j], acc[i][j]);
        }
    }
    #pragma unroll
    for (int i = 0; i < 4; i++)
        #pragma unroll
        for (int j = 0; j < 4; j++)
            g_T[(size_t)(m0 + ty * 4 + i) * G1 + tx * 4 + j] = tanhf(acc[i][j]);
}

// ======================================================================
// Router stage B
// ======================================================================
__global__ __launch_bounds__(128) void router_combine(
    const float* __restrict__ X, const float* __restrict__ W2,
    const float* __restrict__ ceWg, float* __restrict__ logits_out)
{
    const int n = blockIdx.x;
    const int tid = threadIdx.x;
    __shared__ float red[4][128];
    __shared__ float lg[8];

    float pg0 = 0.f, pg1 = 0.f, pg2 = 0.f, pg3 = 0.f;
    for (int k = tid; k < DHID; k += 128) {
        float xv = X[(size_t)n * DHID + k];
        pg0 = fmaf(xv, ceWg[k * 2 + 0], pg0);
        pg1 = fmaf(xv, ceWg[k * 2 + 1], pg1);
        pg2 = fmaf(xv, ceWg[DHID * 2 + k * 2 + 0], pg2);
        pg3 = fmaf(xv, ceWg[DHID * 2 + k * 2 + 1], pg3);
    }
    red[0][tid] = pg0; red[1][tid] = pg1; red[2][tid] = pg2; red[3][tid] = pg3;
    __syncthreads();
    for (int s = 64; s > 0; s >>= 1) {
        if (tid < s) {
            #pragma unroll
            for (int j = 0; j < 4; j++) red[j][tid] += red[j][tid + s];
        }
        __syncthreads();
    }
    if (tid < NE) {
        float s = 0.f;
        #pragma unroll 8
        for (int i = 0; i < G1; i++)
            s = fmaf(g_T[(size_t)n * G1 + i], W2[i * NE + tid], s);
        lg[tid] = s;
        logits_out[(size_t)n * NE + tid] = s;
    }
    __syncthreads();
    if (tid == 0) {
        float p[NE];
        float mx = lg[0];
        #pragma unroll
        for (int e = 1; e < NE; e++) mx = fmaxf(mx, lg[e]);
        float sum = 0.f;
        #pragma unroll
        for (int e = 0; e < NE; e++) { p[e] = __expf(lg[e] - mx); sum += p[e]; }
        float inv = 1.f / sum;
        #pragma unroll
        for (int e = 0; e < NE; e++) p[e] *= inv;
        int i0 = 0;
        #pragma unroll
        for (int e = 1; e < NE; e++) if (p[e] > p[i0]) i0 = e;
        int i1 = (i0 == 0) ? 1 : 0;
        #pragma unroll
        for (int e = 0; e < NE; e++) if (e != i0 && p[e] > p[i1]) i1 = e;
        float w0 = (i0 == NE - 1) ? 0.f : p[i0];
        float w1 = (i1 == NE - 1) ? 0.f : p[i1];
        float winv = 1.f / (w0 + w1);
        w0 *= winv; w1 *= winv;
        float pe[NE];
        #pragma unroll
        for (int e = 0; e < NE; e++) pe[e] = 0.f;
        pe[i0] += w0; pe[i1] += w1;
        float cw0x = 1.f / (1.f + __expf(red[1][0] - red[0][0]));
        float cw1x = 1.f / (1.f + __expf(red[3][0] - red[2][0]));
        g_coef[n * 4 + 0] = pe[0] + pe[2] * cw0x + pe[3] * cw1x;
        g_coef[n * 4 + 1] = pe[2] * (1.f - cw0x);
        g_coef[n * 4 + 2] = pe[3] * (1.f - cw1x);
        g_coef[n * 4 + 3] = pe[4] + pe[5] + pe[6] + pe[7];
    }
}

// ======================================================================
// GEMM 1: H = silu(X@Wg) * (X@Wu)
// CTA: 128 threads (4 warps, 2x2), CTA tile M=128 x mmaN=128 (G|U 64 each).
// Warp tile m64 x n64. 2-stage cp.async, ONE barrier per k-tile, 3 CTAs/SM.
// Correctness of single barrier: the sync at iter kt+1 (after CPA_WAIT)
// separates all warps' compute(kt) reads of buf s from issue(kt+2) writes
// to buf s; issue(kt+1) writes s^1 which compute(kt) never reads.
// ======================================================================
__global__ __launch_bounds__(128, 3) void gemm_gateup()
{
    extern __shared__ unsigned sm[];
    const uint32_t sa = smem_u32(sm);
    const int tid = threadIdx.x;
    const int lane = tid & 31, wid = tid >> 5;
    const int wm = wid & 1, wn = wid >> 1;          // 2x2
    const int g = lane >> 2, tg = lane & 3;
    const int m0 = blockIdx.x * 128;
    const int n0 = blockIdx.y * 64;
    const int KT = DHID / 32;

    float acc[4][8][4] = {};

    auto issue = [&](int kt) {
        int s = kt & 1, k0 = kt * 32;
        #pragma unroll
        for (int i = 0; i < 8; i++) {
            int e = tid + i * 128;
            int r = e >> 3, q = e & 7;
            cpa16(sa + (OFF_A(s) + r * 36 + q * 4) * 4,
                  g_X32 + (size_t)(m0 + r) * DHID + k0 + q * 4);
        }
        #pragma unroll
        for (int i = 0; i < 8; i++) {
            int e = tid + i * 128;
            int kk = e >> 5, c8 = e & 31;
            const float* src = (c8 < 16)
                ? g_Wg32 + (size_t)(k0 + kk) * IEXP + n0 + c8 * 4
                : g_Wu32 + (size_t)(k0 + kk) * IEXP + n0 + (c8 - 16) * 4;
            cpa16(sa + (OFF_B(s) + kk * 136 + c8 * 4) * 4, src);
        }
        CPA_COMMIT();
    };

    issue(0);
    const int arow = wm * 64;
    const int bcol = wn * 64;

    for (int kt = 0; kt < KT; kt++) {
        CPA_WAIT(0);
        __syncthreads();
        if (kt + 1 < KT) issue(kt + 1);
        const unsigned* As = sm + OFF_A(kt & 1);
        const unsigned* Bs = sm + OFF_B(kt & 1);
        #pragma unroll
        for (int ks = 0; ks < 4; ks++) {
            int c = ks * 8 + tg;
            unsigned a[4][4];
            #pragma unroll
            for (int mi = 0; mi < 4; mi++) {
                int r = arow + mi * 16 + g;
                a[mi][0] = As[r * 36 + c];
                a[mi][1] = As[(r + 8) * 36 + c];
                a[mi][2] = As[r * 36 + c + 4];
                a[mi][3] = As[(r + 8) * 36 + c + 4];
            }
            unsigned b[8][2];
            #pragma unroll
            for (int ni = 0; ni < 8; ni++) {
                int nn = bcol + ni * 8 + g;
                b[ni][0] = Bs[c * 136 + nn];
                b[ni][1] = Bs[(c + 4) * 136 + nn];
            }
            #pragma unroll
            for (int mi = 0; mi < 4; mi++)
                #pragma unroll
                for (int ni = 0; ni < 8; ni++)
                    MMA_TF32(acc[mi][ni], a[mi], b[ni]);
        }
    }
    __syncthreads();   // all warps done computing before smem is reused

    // epilogue: acc -> smem [128][132], pair G/U, write g_H (tf32-rounded)
    float* Hs = (float*)sm;
    #pragma unroll
    for (int mi = 0; mi < 4; mi++) {
        int r1 = arow + mi * 16 + g, r2 = r1 + 8;
        #pragma unroll
        for (int ni = 0; ni < 8; ni++) {
            int cc = bcol + ni * 8 + 2 * tg;
            float* c = acc[mi][ni];
            *(float2*)(Hs + r1 * 132 + cc) = make_float2(c[0], c[1]);
            *(float2*)(Hs + r2 * 132 + cc) = make_float2(c[2], c[3]);
        }
    }
    __syncthreads();
    #pragma unroll
    for (int i = 0; i < 64; i++) {
        int e = tid + i * 128;
        int r = e >> 6, cc = e & 63;
        float gv = Hs[r * 132 + cc];
        float uv = Hs[r * 132 + 64 + cc];
        g_H[(size_t)(m0 + r) * IEXP + n0 + cc] = __uint_as_float(f2tf32(siluf(gv) * uv));
    }
}

// ======================================================================
// GEMM 2: out = cs*(H@Wd) + cx*x + cc0*c0 + cc1*c1
// CTA: 128 threads (4 warps, 2x2), tile M=128 x N=128. Warp tile m64xn64.
// 2-stage cp.async, ONE barrier per k-tile, 3 CTAs/SM.
// ======================================================================
__global__ __launch_bounds__(128, 3) void gemm_down(
    const float* __restrict__ X,
    const float* __restrict__ ceC,
    float* __restrict__ out)
{
    extern __shared__ unsigned sm[];
    const uint32_t sa = smem_u32(sm);
    const int tid = threadIdx.x;
    const int lane = tid & 31, wid = tid >> 5;
    const int wm = wid & 1, wn = wid >> 1;
    const int g = lane >> 2, tg = lane & 3;
    const int m0 = blockIdx.x * 128;
    const int n0 = blockIdx.y * 128;
    const int KT = IEXP / 32;

    float acc[4][8][4] = {};

    auto issue = [&](int kt) {
        int s = kt & 1, k0 = kt * 32;
        #pragma unroll
        for (int i = 0; i < 8; i++) {
            int e = tid + i * 128;
            int r = e >> 3, q = e & 7;
            cpa16(sa + (OFF_A(s) + r * 36 + q * 4) * 4,
                  g_H + (size_t)(m0 + r) * IEXP + k0 + q * 4);
        }
        #pragma unroll
        for (int i = 0; i < 8; i++) {
            int e = tid + i * 128;
            int kk = e >> 5, c8 = e & 31;
            cpa16(sa + (OFF_B(s) + kk * 136 + c8 * 4) * 4,
                  g_Wd32 + (size_t)(k0 + kk) * DHID + n0 + c8 * 4);
        }
        CPA_COMMIT();
    };

    issue(0);
    const int arow = wm * 64;
    const int bcol = wn * 64;

    for (int kt = 0; kt < KT; kt++) {
        CPA_WAIT(0);
        __syncthreads();
        if (kt + 1 < KT) issue(kt + 1);
        const unsigned* As = sm + OFF_A(kt & 1);
        const unsigned* Bs = sm + OFF_B(kt & 1);
        #pragma unroll
        for (int ks = 0; ks < 4; ks++) {
            int c = ks * 8 + tg;
            unsigned a[4][4];
            #pragma unroll
            for (int mi = 0; mi < 4; mi++) {
                int r = arow + mi * 16 + g;
                a[mi][0] = As[r * 36 + c];
                a[mi][1] = As[(r + 8) * 36 + c];
                a[mi][2] = As[r * 36 + c + 4];
                a[mi][3] = As[(r + 8) * 36 + c + 4];
            }
            unsigned b[8][2];
            #pragma unroll
            for (int ni = 0; ni < 8; ni++) {
                int nn = bcol + ni * 8 + g;
                b[ni][0] = Bs[c * 136 + nn];
                b[ni][1] = Bs[(c + 4) * 136 + nn];
            }
            #pragma unroll
            for (int mi = 0; mi < 4; mi++)
                #pragma unroll
                for (int ni = 0; ni < 8; ni++)
                    MMA_TF32(acc[mi][ni], a[mi], b[ni]);
        }
    }

    // epilogue: fold routing coefficients, direct from regs (no smem reuse)
    const float* c0 = ceC;
    const float* c1 = ceC + DHID;
    #pragma unroll
    for (int mi = 0; mi < 4; mi++) {
        int r1 = m0 + arow + mi * 16 + g;
        int r2 = r1 + 8;
        float cx1 = g_coef[r1 * 4 + 0], cc01 = g_coef[r1 * 4 + 1],
              cc11 = g_coef[r1 * 4 + 2], cs1 = g_coef[r1 * 4 + 3];
        float cx2 = g_coef[r2 * 4 + 0], cc02 = g_coef[r2 * 4 + 1],
              cc12 = g_coef[r2 * 4 + 2], cs2 = g_coef[r2 * 4 + 3];
        #pragma unroll
        for (int ni = 0; ni < 8; ni++) {
            int nn = n0 + bcol + ni * 8 + 2 * tg;
            float* c = acc[mi][ni];
            float2 x1 = *(const float2*)(X + (size_t)r1 * DHID + nn);
            float2 x2 = *(const float2*)(X + (size_t)r2 * DHID + nn);
            float2 v0 = *(const float2*)(c0 + nn);
            float2 v1 = *(const float2*)(c1 + nn);
            float2 o1, o2;
            o1.x = cs1 * c[0] + cx1 * x1.x + cc01 * v0.x + cc11 * v1.x;
            o1.y = cs1 * c[1] + cx1 * x1.y + cc01 * v0.y + cc11 * v1.y;
            o2.x = cs2 * c[2] + cx2 * x2.x + cc02 * v0.x + cc12 * v1.x;
            o2.y = cs2 * c[3] + cx2 * x2.y + cc02 * v0.y + cc12 * v1.y;
            *(float2*)(out + (size_t)r1 * DHID + nn) = o1;
            *(float2*)(out + (size_t)r2 * DHID + nn) = o2;
        }
    }
}

// ======================================================================
extern "C" void kernel_launch(void* const* d_in, const int* in_sizes, int n_in,
                              void* d_out, int out_size)
{
    const float* X    = (const float*)d_in[0];
    const float* W1   = (const float*)d_in[1];
    const float* W2   = (const float*)d_in[2];
    const float* ceWg = (const float*)d_in[3];
    const float* ceC  = (const float*)d_in[4];
    const float* Wg   = (const float*)d_in[5];
    const float* Wu   = (const float*)d_in[6];
    const float* Wd   = (const float*)d_in[7];
    float* out = (float*)d_out;
    float* logits = out + (size_t)NTOK * DHID;

    cudaFuncSetAttribute(gemm_gateup, cudaFuncAttributeMaxDynamicSharedMemorySize, SMEM_BYTES);
    cudaFuncSetAttribute(gemm_down, cudaFuncAttributeMaxDynamicSharedMemorySize, SMEM_BYTES);

    float *pX32, *pWg32, *pWu32, *pWd32;
    cudaGetSymbolAddress((void**)&pX32, g_X32);
    cudaGetSymbolAddress((void**)&pWg32, g_Wg32);
    cudaGetSymbolAddress((void**)&pWu32, g_Wu32);
    cudaGetSymbolAddress((void**)&pWd32, g_Wd32);

    // Launch order chosen so gemm_gateup is launch index 5 (ncu -s 5 -c 1
    // captures it). Dependencies: gateup needs X32/Wg32/Wu32 (idx 0-2);
    // down needs Wd32 (idx 3), g_H (idx 5), g_coef (idx 6).
    round_tf32_k<<<1024, 256>>>(X,  pX32,  NTOK * DHID / 4);    // 0
    round_tf32_k<<<2048, 256>>>(Wg, pWg32, DHID * IEXP / 4);    // 1
    round_tf32_k<<<2048, 256>>>(Wu, pWu32, DHID * IEXP / 4);    // 2
    round_tf32_k<<<2048, 256>>>(Wd, pWd32, IEXP * DHID / 4);    // 3
    router_gemm_tanh<<<NTOK / 64, 256>>>(X, W1);                // 4
    gemm_gateup<<<dim3(NTOK / 128, IEXP / 64), 128, SMEM_BYTES>>>();  // 5 <- profiled
    router_combine<<<NTOK, 128>>>(X, W2, ceWg, logits);         // 6
    gemm_down<<<dim3(NTOK / 128, DHID / 128), 128, SMEM_BYTES>>>(X, ceC, out);  // 7
}